// round 6
// baseline (speedup 1.0000x reference)
#include <cuda_runtime.h>
#include <cuda_bf16.h>
#include <cstdint>

// ---------------------------------------------------------------------------
// MoE LoRA delta via warp-level bf16 mma.sync (sm_100-safe; no tcgen05).
//   x (T=8192, D=4096) f32, router_w (4, D), A (4,16,D), B (4,4096,16)
// fp32 precision recovered by hi/lo bf16 split: P = Xh*Wh + Xh*Wl + Xl*Wh.
// Pipeline:
//   prepA : A_ext = [A(64) ; router_w(4) ; 0(4)] -> bf16 hi/lo, K-major u32 pairs
//   prepB : B -> Bf (o, er) bf16 hi/lo
//   mid   : midp[split] = x @ A_ext^T   (N=72 incl. router logits), mma.sync
//   gates : top-2 softmax from logit cols 64..67 (scaled by 4.0)
//   comb  : gmid = gate * sum_split midp -> bf16 hi/lo
//   out   : out = gmid @ Bf^T           (K=64), mma.sync
// ---------------------------------------------------------------------------

#define D_DIM   4096
#define O_DIM   4096
#define MAXT    8192
#define LSCALE  4.0f
#define KSPLIT  4
#define NEXT    72            // 64 lora + 4 router + 4 pad
#define KU      (D_DIM / 2)   // u32 (bf16 pair) per A_ext row

// ------------------------- device scratch (static) -------------------------
__device__ float    g_gates[MAXT][4];
__device__ float    g_midp[KSPLIT][MAXT][NEXT];   // 9.4 MB
__device__ uint32_t g_Axh[NEXT][KU];              // A_ext hi  (0.6 MB)
__device__ uint32_t g_Axl[NEXT][KU];              // A_ext lo
__device__ uint32_t g_Bh[O_DIM][32];              // Bf hi (0.5 MB)
__device__ uint32_t g_Bl[O_DIM][32];
__device__ uint32_t g_Gh[MAXT][32];               // gmid hi (1 MB)
__device__ uint32_t g_Gl[MAXT][32];

// ------------------------------ helpers ------------------------------------
// split fp32 pair into packed-bf16 hi / lo words
static __device__ __forceinline__ void split2(float a, float b,
                                              uint32_t& hi, uint32_t& lo) {
    __nv_bfloat16 ah = __float2bfloat16_rn(a);
    __nv_bfloat16 bh = __float2bfloat16_rn(b);
    __nv_bfloat16 al = __float2bfloat16_rn(a - __bfloat162float(ah));
    __nv_bfloat16 bl = __float2bfloat16_rn(b - __bfloat162float(bh));
    __nv_bfloat162 H; H.x = ah; H.y = bh;
    __nv_bfloat162 L; L.x = al; L.y = bl;
    hi = reinterpret_cast<uint32_t&>(H);
    lo = reinterpret_cast<uint32_t&>(L);
}

// D += A(16x16 bf16, row-major) * B(16x8 bf16, col-major), f32 accumulate
static __device__ __forceinline__ void mma_bf16(float* c,
        uint32_t a0, uint32_t a1, uint32_t a2, uint32_t a3,
        uint32_t b0, uint32_t b1) {
    asm volatile(
        "mma.sync.aligned.m16n8k16.row.col.f32.bf16.bf16.f32 "
        "{%0,%1,%2,%3},{%4,%5,%6,%7},{%8,%9},{%0,%1,%2,%3};"
        : "+f"(c[0]), "+f"(c[1]), "+f"(c[2]), "+f"(c[3])
        : "r"(a0), "r"(a1), "r"(a2), "r"(a3), "r"(b0), "r"(b1));
}

// ---------------------------------------------------------------------------
// prepA: A_ext (72, 4096) f32 -> hi/lo bf16 u32 pairs, K-major.
// ---------------------------------------------------------------------------
__global__ __launch_bounds__(256)
void prepA_kernel(const float* __restrict__ A, const float* __restrict__ rw)
{
    int idx = blockIdx.x * blockDim.x + threadIdx.x;   // NEXT * 1024 quads
    if (idx >= NEXT * 1024) return;
    int row = idx >> 10;
    int q   = idx & 1023;
    float4 v = make_float4(0.f, 0.f, 0.f, 0.f);
    if (row < 64)
        v = *reinterpret_cast<const float4*>(A + (size_t)row * D_DIM + q * 4);
    else if (row < 68)
        v = *reinterpret_cast<const float4*>(rw + (size_t)(row - 64) * D_DIM + q * 4);
    uint32_t h0, l0, h1, l1;
    split2(v.x, v.y, h0, l0);
    split2(v.z, v.w, h1, l1);
    *reinterpret_cast<uint2*>(&g_Axh[row][q * 2]) = make_uint2(h0, h1);
    *reinterpret_cast<uint2*>(&g_Axl[row][q * 2]) = make_uint2(l0, l1);
}

// ---------------------------------------------------------------------------
// prepB: B (E,O,R) f32 -> Bf[o][er] bf16 hi/lo, er = e*16+r.
// ---------------------------------------------------------------------------
__global__ __launch_bounds__(256)
void prepB_kernel(const float* __restrict__ B)
{
    int o = blockIdx.x * blockDim.x + threadIdx.x;
    if (o >= O_DIM) return;
    #pragma unroll
    for (int e = 0; e < 4; e++) {
        const float4* src = reinterpret_cast<const float4*>(
            B + ((size_t)e * O_DIM + o) * 16);
        #pragma unroll
        for (int i = 0; i < 4; i++) {
            float4 v = src[i];
            uint32_t h0, l0, h1, l1;
            split2(v.x, v.y, h0, l0);
            split2(v.z, v.w, h1, l1);
            *reinterpret_cast<uint2*>(&g_Bh[o][e * 8 + i * 2]) = make_uint2(h0, h1);
            *reinterpret_cast<uint2*>(&g_Bl[o][e * 8 + i * 2]) = make_uint2(l0, l1);
        }
    }
}

// ---------------------------------------------------------------------------
// mid: midp[split] = x @ A_ext^T.  grid (T/128, KSPLIT), 256 thr (8 warps).
//   Warp w owns rows w*16..+15; N=72 -> 9 n-tiles; K chunk 64 (4 ksteps).
//   x staged to smem as bf16 hi/lo u32 pairs; A_ext frags direct LDG (L1/L2).
// ---------------------------------------------------------------------------
__global__ __launch_bounds__(256, 1)
void mid_kernel(const float* __restrict__ x)
{
    __shared__ uint32_t xsh[128][36];   // pad 36 -> conflict-free frag reads
    __shared__ uint32_t xsl[128][36];

    const int tid  = threadIdx.x;
    const int w    = tid >> 5;
    const int lane = tid & 31;
    const int g    = lane >> 2;
    const int tig  = lane & 3;
    const int t0   = blockIdx.x * 128;
    const int split = blockIdx.y;
    const int kbase = split * (D_DIM / KSPLIT);

    float acc[9][4] = {};

    for (int c = 0; c < (D_DIM / KSPLIT) / 64; c++) {   // 16 chunks
        const int k0 = kbase + c * 64;
        __syncthreads();
        // stage x chunk (128 rows x 64 k): f32 -> bf16 hi/lo
        #pragma unroll
        for (int p = 0; p < 8; p++) {
            int idx = tid + p * 256;
            int row = idx >> 4;
            int q   = idx & 15;
            float4 v = *reinterpret_cast<const float4*>(
                x + (size_t)(t0 + row) * D_DIM + k0 + q * 4);
            uint32_t h0, l0, h1, l1;
            split2(v.x, v.y, h0, l0);
            split2(v.z, v.w, h1, l1);
            *reinterpret_cast<uint2*>(&xsh[row][q * 2]) = make_uint2(h0, h1);
            *reinterpret_cast<uint2*>(&xsl[row][q * 2]) = make_uint2(l0, l1);
        }
        __syncthreads();

        const int r0 = w * 16 + g;
        #pragma unroll
        for (int ks = 0; ks < 4; ks++) {
            const int ki = ks * 8 + tig;
            uint32_t ah0 = xsh[r0][ki],     ah1 = xsh[r0 + 8][ki];
            uint32_t ah2 = xsh[r0][ki + 4], ah3 = xsh[r0 + 8][ki + 4];
            uint32_t al0 = xsl[r0][ki],     al1 = xsl[r0 + 8][ki];
            uint32_t al2 = xsl[r0][ki + 4], al3 = xsl[r0 + 8][ki + 4];
            const int kq = (k0 >> 1) + ks * 8 + tig;
            #pragma unroll
            for (int nt = 0; nt < 9; nt++) {
                const int n = nt * 8 + g;
                uint32_t bh0 = g_Axh[n][kq], bh1 = g_Axh[n][kq + 4];
                uint32_t bl0 = g_Axl[n][kq], bl1 = g_Axl[n][kq + 4];
                mma_bf16(acc[nt], ah0, ah1, ah2, ah3, bh0, bh1);
                mma_bf16(acc[nt], ah0, ah1, ah2, ah3, bl0, bl1);
                mma_bf16(acc[nt], al0, al1, al2, al3, bh0, bh1);
            }
        }
    }

    const int r0 = t0 + w * 16 + g;
    #pragma unroll
    for (int nt = 0; nt < 9; nt++) {
        int col = nt * 8 + 2 * tig;
        *reinterpret_cast<float2*>(&g_midp[split][r0][col]) =
            make_float2(acc[nt][0], acc[nt][1]);
        *reinterpret_cast<float2*>(&g_midp[split][r0 + 8][col]) =
            make_float2(acc[nt][2], acc[nt][3]);
    }
}

// ---------------------------------------------------------------------------
// gates: per token, sum logit partials (cols 64..67), top-2 softmax * LSCALE
// ---------------------------------------------------------------------------
__global__ __launch_bounds__(256)
void gates_kernel(int T)
{
    int t = blockIdx.x * blockDim.x + threadIdx.x;
    if (t >= T) return;
    float l[4];
    #pragma unroll
    for (int e = 0; e < 4; e++) {
        float s = 0.f;
        #pragma unroll
        for (int p = 0; p < KSPLIT; p++) s += g_midp[p][t][64 + e];
        l[e] = s;
    }
    int i1 = 0; float v1 = l[0];
    if (l[1] > v1) { v1 = l[1]; i1 = 1; }
    if (l[2] > v1) { v1 = l[2]; i1 = 2; }
    if (l[3] > v1) { v1 = l[3]; i1 = 3; }
    int i2 = -1; float v2 = -3.4e38f;
    #pragma unroll
    for (int e = 0; e < 4; e++)
        if (e != i1 && l[e] > v2) { v2 = l[e]; i2 = e; }
    float e2  = __expf(v2 - v1);
    float inv = 1.0f / (1.0f + e2);
    float gg[4] = {0.f, 0.f, 0.f, 0.f};
    gg[i1] = LSCALE * inv;
    gg[i2] = LSCALE * e2 * inv;
    reinterpret_cast<float4*>(g_gates)[t] = make_float4(gg[0], gg[1], gg[2], gg[3]);
}

// ---------------------------------------------------------------------------
// comb: gmid = gate * sum_split midp (cols 0..63) -> bf16 hi/lo u32 pairs
// ---------------------------------------------------------------------------
__global__ __launch_bounds__(256)
void comb_kernel(int T)
{
    int idx = blockIdx.x * blockDim.x + threadIdx.x;   // T * 16
    if (idx >= T * 16) return;
    int t = idx >> 4;
    int j = idx & 15;
    float4 s = make_float4(0.f, 0.f, 0.f, 0.f);
    #pragma unroll
    for (int p = 0; p < KSPLIT; p++) {
        float4 m = *reinterpret_cast<const float4*>(&g_midp[p][t][j * 4]);
        s.x += m.x; s.y += m.y; s.z += m.z; s.w += m.w;
    }
    float gv = g_gates[t][j >> 2];
    uint32_t h0, l0, h1, l1;
    split2(s.x * gv, s.y * gv, h0, l0);
    split2(s.z * gv, s.w * gv, h1, l1);
    *reinterpret_cast<uint2*>(&g_Gh[t][j * 2]) = make_uint2(h0, h1);
    *reinterpret_cast<uint2*>(&g_Gl[t][j * 2]) = make_uint2(l0, l1);
}

// ---------------------------------------------------------------------------
// out: out = gmid @ Bf^T.  grid (O/128, T/128), 256 thr (8 warps).
//   Warp w: rows w*16..+15 of 128-row tile, all 128 n-cols (16 n-tiles).
//   K = 64 -> 4 ksteps.  All fragments direct LDG (operands L2-resident).
// ---------------------------------------------------------------------------
__global__ __launch_bounds__(256, 1)
void out_kernel(float* __restrict__ out)
{
    const int tid  = threadIdx.x;
    const int w    = tid >> 5;
    const int lane = tid & 31;
    const int g    = lane >> 2;
    const int tig  = lane & 3;
    const int n0   = blockIdx.x * 128;
    const int t0   = blockIdx.y * 128;
    const int r0   = t0 + w * 16 + g;

    float acc[16][4] = {};

    #pragma unroll
    for (int ks = 0; ks < 4; ks++) {
        const int ki = ks * 8 + tig;
        uint32_t ah0 = g_Gh[r0][ki],     ah1 = g_Gh[r0 + 8][ki];
        uint32_t ah2 = g_Gh[r0][ki + 4], ah3 = g_Gh[r0 + 8][ki + 4];
        uint32_t al0 = g_Gl[r0][ki],     al1 = g_Gl[r0 + 8][ki];
        uint32_t al2 = g_Gl[r0][ki + 4], al3 = g_Gl[r0 + 8][ki + 4];
        #pragma unroll
        for (int nt = 0; nt < 16; nt++) {
            const int n = n0 + nt * 8 + g;
            uint32_t bh0 = g_Bh[n][ki], bh1 = g_Bh[n][ki + 4];
            uint32_t bl0 = g_Bl[n][ki], bl1 = g_Bl[n][ki + 4];
            mma_bf16(acc[nt], ah0, ah1, ah2, ah3, bh0, bh1);
            mma_bf16(acc[nt], ah0, ah1, ah2, ah3, bl0, bl1);
            mma_bf16(acc[nt], al0, al1, al2, al3, bh0, bh1);
        }
    }

    #pragma unroll
    for (int nt = 0; nt < 16; nt++) {
        int col = n0 + nt * 8 + 2 * tig;
        *reinterpret_cast<float2*>(out + (size_t)r0 * O_DIM + col) =
            make_float2(acc[nt][0], acc[nt][1]);
        *reinterpret_cast<float2*>(out + (size_t)(r0 + 8) * O_DIM + col) =
            make_float2(acc[nt][2], acc[nt][3]);
    }
}

// ---------------------------------------------------------------------------
// launch
// ---------------------------------------------------------------------------
extern "C" void kernel_launch(void* const* d_in, const int* in_sizes, int n_in,
                              void* d_out, int out_size)
{
    const float* x  = (const float*)d_in[0];   // (T, D)
    const float* rw = (const float*)d_in[1];   // (E, D)
    const float* A  = (const float*)d_in[2];   // (E, R, D) == (64, D)
    const float* B  = (const float*)d_in[3];   // (E, O, R)
    float* out = (float*)d_out;                // (T, O)

    int T = in_sizes[0] / D_DIM;               // 8192

    prepA_kernel<<<(NEXT * 1024 + 255) / 256, 256>>>(A, rw);
    prepB_kernel<<<(O_DIM + 255) / 256, 256>>>(B);
    mid_kernel<<<dim3(T / 128, KSPLIT), 256>>>(x);
    gates_kernel<<<(T + 255) / 256, 256>>>(T);
    comb_kernel<<<(T * 16 + 255) / 256, 256>>>(T);
    out_kernel<<<dim3(O_DIM / 128, T / 128), 256>>>(out);
}

// round 7
// speedup vs baseline: 3.2258x; 3.2258x over previous
#include <cuda_runtime.h>
#include <cuda_bf16.h>
#include <cstdint>

// ---------------------------------------------------------------------------
// MoE LoRA delta via mma.sync bf16 hi/lo split, smem-staged ldmatrix feeds.
//   x (T=8192, D=4096) f32, router_w (4, D), A (4,16,D), B (4,4096,16)
// P = Xh*Wh + Xh*Wl + Xl*Wh  (fp32 accum)  -> rel_err ~1e-5
// Pipeline:
//   prepA : A_ext = [A(64); router_w(4); 0(12)] -> bf16 hi/lo u32, K-major
//   prepB : B -> Bf[o][er] bf16 hi/lo u32
//   mid   : midp[split] = x @ A_ext^T  (N=80 tiles, store 72; router fused)
//   comb  : gates (top-2 softmax * 4.0) + gmid = gate * sum_split midp -> bf16
//   out   : out = gmid @ Bf^T  (K=64 single shot)
// ---------------------------------------------------------------------------

#define D_DIM   4096
#define O_DIM   4096
#define MAXT    8192
#define LSCALE  4.0f
#define KSPLIT  4
#define NEXT    80            // 64 lora + 4 router + 12 pad (10 n-tiles)
#define NSTORE  72            // cols written to midp (9 tiles)
#define KU      (D_DIM / 2)   // u32 per A_ext row
#define S       72            // smem row stride in bf16 halves (144 B)

// ------------------------- device scratch (static) -------------------------
__device__ float    g_midp[KSPLIT][MAXT][NSTORE];   // 9.4 MB
__device__ uint32_t g_Axh[NEXT][KU];                // 0.64 MB
__device__ uint32_t g_Axl[NEXT][KU];
__device__ uint32_t g_Bh[O_DIM][32];                // 0.5 MB
__device__ uint32_t g_Bl[O_DIM][32];
__device__ uint32_t g_Gh[MAXT][32];                 // 1 MB
__device__ uint32_t g_Gl[MAXT][32];

// ------------------------------ helpers ------------------------------------
static __device__ __forceinline__ uint32_t smem_u32(const void* p) {
    uint32_t a;
    asm("{ .reg .u64 t; cvta.to.shared.u64 t, %1; cvt.u32.u64 %0, t; }"
        : "=r"(a) : "l"(p));
    return a;
}
static __device__ __forceinline__ void split2(float a, float b,
                                              uint32_t& hi, uint32_t& lo) {
    __nv_bfloat16 ah = __float2bfloat16_rn(a);
    __nv_bfloat16 bh = __float2bfloat16_rn(b);
    __nv_bfloat16 al = __float2bfloat16_rn(a - __bfloat162float(ah));
    __nv_bfloat16 bl = __float2bfloat16_rn(b - __bfloat162float(bh));
    __nv_bfloat162 H; H.x = ah; H.y = bh;
    __nv_bfloat162 L; L.x = al; L.y = bl;
    hi = reinterpret_cast<uint32_t&>(H);
    lo = reinterpret_cast<uint32_t&>(L);
}
static __device__ __forceinline__ void mma_bf16(float* c,
        uint32_t a0, uint32_t a1, uint32_t a2, uint32_t a3,
        uint32_t b0, uint32_t b1) {
    asm volatile(
        "mma.sync.aligned.m16n8k16.row.col.f32.bf16.bf16.f32 "
        "{%0,%1,%2,%3},{%4,%5,%6,%7},{%8,%9},{%0,%1,%2,%3};"
        : "+f"(c[0]), "+f"(c[1]), "+f"(c[2]), "+f"(c[3])
        : "r"(a0), "r"(a1), "r"(a2), "r"(a3), "r"(b0), "r"(b1));
}
#define LDSM_X4(d0, d1, d2, d3, a)                                           \
    asm volatile("ldmatrix.sync.aligned.m8n8.x4.shared.b16 {%0,%1,%2,%3}, [%4];" \
                 : "=r"(d0), "=r"(d1), "=r"(d2), "=r"(d3) : "r"(a))

// ---------------------------------------------------------------------------
// prepA: A_ext (80, 4096) -> hi/lo bf16 u32 pairs, K-major.
// ---------------------------------------------------------------------------
__global__ __launch_bounds__(256)
void prepA_kernel(const float* __restrict__ A, const float* __restrict__ rw)
{
    int idx = blockIdx.x * blockDim.x + threadIdx.x;   // NEXT * 1024 quads
    if (idx >= NEXT * 1024) return;
    int row = idx >> 10;
    int q   = idx & 1023;
    float4 v = make_float4(0.f, 0.f, 0.f, 0.f);
    if (row < 64)
        v = *reinterpret_cast<const float4*>(A + (size_t)row * D_DIM + q * 4);
    else if (row < 68)
        v = *reinterpret_cast<const float4*>(rw + (size_t)(row - 64) * D_DIM + q * 4);
    uint32_t h0, l0, h1, l1;
    split2(v.x, v.y, h0, l0);
    split2(v.z, v.w, h1, l1);
    *reinterpret_cast<uint2*>(&g_Axh[row][q * 2]) = make_uint2(h0, h1);
    *reinterpret_cast<uint2*>(&g_Axl[row][q * 2]) = make_uint2(l0, l1);
}

// ---------------------------------------------------------------------------
// prepB: B (E,O,R) -> Bf[o][er] bf16 hi/lo.
// ---------------------------------------------------------------------------
__global__ __launch_bounds__(256)
void prepB_kernel(const float* __restrict__ B)
{
    int o = blockIdx.x * blockDim.x + threadIdx.x;
    if (o >= O_DIM) return;
    #pragma unroll
    for (int e = 0; e < 4; e++) {
        const float4* src = reinterpret_cast<const float4*>(
            B + ((size_t)e * O_DIM + o) * 16);
        #pragma unroll
        for (int i = 0; i < 4; i++) {
            float4 v = src[i];
            uint32_t h0, l0, h1, l1;
            split2(v.x, v.y, h0, l0);
            split2(v.z, v.w, h1, l1);
            *reinterpret_cast<uint2*>(&g_Bh[o][e * 8 + i * 2]) = make_uint2(h0, h1);
            *reinterpret_cast<uint2*>(&g_Bl[o][e * 8 + i * 2]) = make_uint2(l0, l1);
        }
    }
}

// ---------------------------------------------------------------------------
// mid: midp[split] = x @ A_ext^T.  grid (T/128, KSPLIT), 256 thr.
//   smem: xh|xl (128 x S) + ah|al (80 x S), stride S=72 halves -> 58.5 KB.
// ---------------------------------------------------------------------------
#define MID_DSM ((2 * 128 + 2 * NEXT) * S * 2)

__global__ __launch_bounds__(256, 2)
void mid_kernel(const float* __restrict__ x)
{
    extern __shared__ __align__(16) uint16_t sm_mid[];
    const uint32_t base = smem_u32(sm_mid);
    uint32_t* xh32 = reinterpret_cast<uint32_t*>(sm_mid);
    uint32_t* xl32 = xh32 + 128 * (S / 2);
    uint32_t* ah32 = xl32 + 128 * (S / 2);
    uint32_t* al32 = ah32 + NEXT * (S / 2);
    const uint32_t xh_b = base;
    const uint32_t xl_b = base + 128 * S * 2;
    const uint32_t ah_b = base + 256 * S * 2;
    const uint32_t al_b = base + (256 + NEXT) * S * 2;

    const int tid  = threadIdx.x;
    const int w    = tid >> 5;
    const int lane = tid & 31;
    const int g    = lane >> 2;
    const int tig  = lane & 3;
    const int t0   = blockIdx.x * 128;
    const int split = blockIdx.y;
    const int kbase = split * (D_DIM / KSPLIT);

    // ldmatrix per-lane address components
    const int arow = (lane & 7) + ((lane >> 3) & 1) * 8;   // A-frag (x tile)
    const int acol = (lane >> 4) * 8;
    const int brow = (lane & 7) + (lane >> 4) * 8;         // B-frag (A_ext tile)
    const int bcol = ((lane >> 3) & 1) * 8;
    const uint32_t axh = xh_b + (uint32_t)(((w * 16 + arow) * S + acol) * 2);
    const uint32_t axl = xl_b + (uint32_t)(((w * 16 + arow) * S + acol) * 2);
    const uint32_t bah = ah_b + (uint32_t)((brow * S + bcol) * 2);
    const uint32_t bal = al_b + (uint32_t)((brow * S + bcol) * 2);

    // staging index precompute
    const int xr = tid >> 4, xq = tid & 15;       // x: row, float4-col
    const int ar = tid >> 5, aj = tid & 31;       // A: row base, u32-col

    float acc[10][4] = {};

    for (int c = 0; c < (D_DIM / KSPLIT) / 64; c++) {   // 16 chunks
        const int k0  = kbase + c * 64;
        const int kq0 = k0 >> 1;

        // issue global loads into registers (overlaps with sync wait)
        float4 xv[8];
        #pragma unroll
        for (int p = 0; p < 8; p++)
            xv[p] = *reinterpret_cast<const float4*>(
                x + (size_t)(t0 + xr + p * 16) * D_DIM + k0 + xq * 4);
        uint32_t avh[10], avl[10];
        #pragma unroll
        for (int p = 0; p < 10; p++) {
            int row = ar + p * 8;
            avh[p] = g_Axh[row][kq0 + aj];
            avl[p] = g_Axl[row][kq0 + aj];
        }

        __syncthreads();   // prior chunk's compute done reading smem

        #pragma unroll
        for (int p = 0; p < 8; p++) {
            uint32_t h0, l0, h1, l1;
            split2(xv[p].x, xv[p].y, h0, l0);
            split2(xv[p].z, xv[p].w, h1, l1);
            int u = (xr + p * 16) * (S / 2) + xq * 2;
            *reinterpret_cast<uint2*>(&xh32[u]) = make_uint2(h0, h1);
            *reinterpret_cast<uint2*>(&xl32[u]) = make_uint2(l0, l1);
        }
        #pragma unroll
        for (int p = 0; p < 10; p++) {
            int u = (ar + p * 8) * (S / 2) + aj;
            ah32[u] = avh[p];
            al32[u] = avl[p];
        }
        __syncthreads();

        #pragma unroll
        for (int ks = 0; ks < 4; ks++) {
            const uint32_t kb = (uint32_t)(ks * 32);   // 16 halves
            uint32_t ah0, ah1, ah2, ah3, al0, al1, al2, al3;
            LDSM_X4(ah0, ah1, ah2, ah3, axh + kb);
            LDSM_X4(al0, al1, al2, al3, axl + kb);
            #pragma unroll
            for (int ntp = 0; ntp < 5; ntp++) {
                const uint32_t bo = (uint32_t)(ntp * 16 * S * 2) + kb;
                uint32_t bh0, bh1, bh2, bh3, bl0, bl1, bl2, bl3;
                LDSM_X4(bh0, bh1, bh2, bh3, bah + bo);
                LDSM_X4(bl0, bl1, bl2, bl3, bal + bo);
                mma_bf16(acc[2 * ntp],     ah0, ah1, ah2, ah3, bh0, bh1);
                mma_bf16(acc[2 * ntp],     ah0, ah1, ah2, ah3, bl0, bl1);
                mma_bf16(acc[2 * ntp],     al0, al1, al2, al3, bh0, bh1);
                mma_bf16(acc[2 * ntp + 1], ah0, ah1, ah2, ah3, bh2, bh3);
                mma_bf16(acc[2 * ntp + 1], ah0, ah1, ah2, ah3, bl2, bl3);
                mma_bf16(acc[2 * ntp + 1], al0, al1, al2, al3, bh2, bh3);
            }
        }
    }

    const int r0 = t0 + w * 16 + g;
    #pragma unroll
    for (int nt = 0; nt < 9; nt++) {               // skip pad tile 9
        int col = nt * 8 + 2 * tig;
        *reinterpret_cast<float2*>(&g_midp[split][r0][col]) =
            make_float2(acc[nt][0], acc[nt][1]);
        *reinterpret_cast<float2*>(&g_midp[split][r0 + 8][col]) =
            make_float2(acc[nt][2], acc[nt][3]);
    }
}

// ---------------------------------------------------------------------------
// comb: gates (from midp cols 64..67) + gmid -> bf16 hi/lo.  T*16 threads.
// ---------------------------------------------------------------------------
__global__ __launch_bounds__(256)
void comb_kernel(int T)
{
    int idx = blockIdx.x * blockDim.x + threadIdx.x;
    if (idx >= T * 16) return;
    int t = idx >> 4;
    int j = idx & 15;

    float l[4];
    #pragma unroll
    for (int e = 0; e < 4; e++) {
        float s = 0.f;
        #pragma unroll
        for (int p = 0; p < KSPLIT; p++) s += g_midp[p][t][64 + e];
        l[e] = s;
    }
    int i1 = 0; float v1 = l[0];
    if (l[1] > v1) { v1 = l[1]; i1 = 1; }
    if (l[2] > v1) { v1 = l[2]; i1 = 2; }
    if (l[3] > v1) { v1 = l[3]; i1 = 3; }
    int i2 = -1; float v2 = -3.4e38f;
    #pragma unroll
    for (int e = 0; e < 4; e++)
        if (e != i1 && l[e] > v2) { v2 = l[e]; i2 = e; }
    float e2  = __expf(v2 - v1);
    float inv = 1.0f / (1.0f + e2);
    int e_mine = j >> 2;
    float gv = (e_mine == i1) ? LSCALE * inv
             : (e_mine == i2) ? LSCALE * e2 * inv : 0.f;

    float4 s = make_float4(0.f, 0.f, 0.f, 0.f);
    #pragma unroll
    for (int p = 0; p < KSPLIT; p++) {
        float4 m = *reinterpret_cast<const float4*>(&g_midp[p][t][j * 4]);
        s.x += m.x; s.y += m.y; s.z += m.z; s.w += m.w;
    }
    uint32_t h0, l0, h1, l1;
    split2(s.x * gv, s.y * gv, h0, l0);
    split2(s.z * gv, s.w * gv, h1, l1);
    *reinterpret_cast<uint2*>(&g_Gh[t][j * 2]) = make_uint2(h0, h1);
    *reinterpret_cast<uint2*>(&g_Gl[t][j * 2]) = make_uint2(l0, l1);
}

// ---------------------------------------------------------------------------
// out: out = gmid @ Bf^T, 128x128 tile, K=64 single shot.
//   smem: gh|gl|bh|bl (each 128 x S) = 72 KB.  grid (O/128, T/128), 256 thr.
// ---------------------------------------------------------------------------
#define OUT_DSM (4 * 128 * S * 2)

__global__ __launch_bounds__(256, 2)
void out_kernel(float* __restrict__ out)
{
    extern __shared__ __align__(16) uint16_t sm_out[];
    const uint32_t base = smem_u32(sm_out);
    uint32_t* gh32 = reinterpret_cast<uint32_t*>(sm_out);
    uint32_t* gl32 = gh32 + 128 * (S / 2);
    uint32_t* bh32 = gl32 + 128 * (S / 2);
    uint32_t* bl32 = bh32 + 128 * (S / 2);
    const uint32_t gh_b = base;
    const uint32_t gl_b = base + 128 * S * 2;
    const uint32_t bh_b = base + 256 * S * 2;
    const uint32_t bl_b = base + 384 * S * 2;

    const int tid  = threadIdx.x;
    const int w    = tid >> 5;
    const int lane = tid & 31;
    const int g    = lane >> 2;
    const int tig  = lane & 3;
    const int n0   = blockIdx.x * 128;
    const int t0   = blockIdx.y * 128;

    // stage all four tiles (coalesced 128B rows)
    {
        const int r = tid >> 5, j = tid & 31;
        #pragma unroll
        for (int p = 0; p < 16; p++) {
            int row = r + p * 8;
            int u = row * (S / 2) + j;
            gh32[u] = g_Gh[t0 + row][j];
            gl32[u] = g_Gl[t0 + row][j];
            bh32[u] = g_Bh[n0 + row][j];
            bl32[u] = g_Bl[n0 + row][j];
        }
    }
    __syncthreads();

    const int arow = (lane & 7) + ((lane >> 3) & 1) * 8;
    const int acol = (lane >> 4) * 8;
    const int brow = (lane & 7) + (lane >> 4) * 8;
    const int bcol = ((lane >> 3) & 1) * 8;
    const uint32_t agh = gh_b + (uint32_t)(((w * 16 + arow) * S + acol) * 2);
    const uint32_t agl = gl_b + (uint32_t)(((w * 16 + arow) * S + acol) * 2);
    const uint32_t bbh = bh_b + (uint32_t)((brow * S + bcol) * 2);
    const uint32_t bbl = bl_b + (uint32_t)((brow * S + bcol) * 2);

    float acc[16][4] = {};

    #pragma unroll
    for (int ks = 0; ks < 4; ks++) {
        const uint32_t kb = (uint32_t)(ks * 32);
        uint32_t ah0, ah1, ah2, ah3, al0, al1, al2, al3;
        LDSM_X4(ah0, ah1, ah2, ah3, agh + kb);
        LDSM_X4(al0, al1, al2, al3, agl + kb);
        #pragma unroll
        for (int ntp = 0; ntp < 8; ntp++) {
            const uint32_t bo = (uint32_t)(ntp * 16 * S * 2) + kb;
            uint32_t bh0, bh1, bh2, bh3, bl0, bl1, bl2, bl3;
            LDSM_X4(bh0, bh1, bh2, bh3, bbh + bo);
            LDSM_X4(bl0, bl1, bl2, bl3, bbl + bo);
            mma_bf16(acc[2 * ntp],     ah0, ah1, ah2, ah3, bh0, bh1);
            mma_bf16(acc[2 * ntp],     ah0, ah1, ah2, ah3, bl0, bl1);
            mma_bf16(acc[2 * ntp],     al0, al1, al2, al3, bh0, bh1);
            mma_bf16(acc[2 * ntp + 1], ah0, ah1, ah2, ah3, bh2, bh3);
            mma_bf16(acc[2 * ntp + 1], ah0, ah1, ah2, ah3, bl2, bl3);
            mma_bf16(acc[2 * ntp + 1], al0, al1, al2, al3, bh2, bh3);
        }
    }

    const int r0 = t0 + w * 16 + g;
    #pragma unroll
    for (int nt = 0; nt < 16; nt++) {
        int col = n0 + nt * 8 + 2 * tig;
        *reinterpret_cast<float2*>(out + (size_t)r0 * O_DIM + col) =
            make_float2(acc[nt][0], acc[nt][1]);
        *reinterpret_cast<float2*>(out + (size_t)(r0 + 8) * O_DIM + col) =
            make_float2(acc[nt][2], acc[nt][3]);
    }
}

// ---------------------------------------------------------------------------
// launch
// ---------------------------------------------------------------------------
extern "C" void kernel_launch(void* const* d_in, const int* in_sizes, int n_in,
                              void* d_out, int out_size)
{
    const float* x  = (const float*)d_in[0];   // (T, D)
    const float* rw = (const float*)d_in[1];   // (E, D)
    const float* A  = (const float*)d_in[2];   // (E, R, D) == (64, D)
    const float* B  = (const float*)d_in[3];   // (E, O, R)
    float* out = (float*)d_out;                // (T, O)

    int T = in_sizes[0] / D_DIM;               // 8192

    cudaFuncSetAttribute(mid_kernel, cudaFuncAttributeMaxDynamicSharedMemorySize, MID_DSM);
    cudaFuncSetAttribute(out_kernel, cudaFuncAttributeMaxDynamicSharedMemorySize, OUT_DSM);

    prepA_kernel<<<(NEXT * 1024 + 255) / 256, 256>>>(A, rw);
    prepB_kernel<<<(O_DIM + 255) / 256, 256>>>(B);
    mid_kernel<<<dim3(T / 128, KSPLIT), 256, MID_DSM>>>(x);
    comb_kernel<<<(T * 16 + 255) / 256, 256>>>(T);
    out_kernel<<<dim3(O_DIM / 128, T / 128), 256, OUT_DSM>>>(out);
}

// round 9
// speedup vs baseline: 3.3342x; 1.0336x over previous
#include <cuda_runtime.h>
#include <cuda_bf16.h>
#include <cstdint>

// ---------------------------------------------------------------------------
// MoE LoRA delta via mma.sync bf16 hi/lo split, smem-staged ldmatrix feeds.
//   x (T=8192, D=4096) f32, router_w (4, D), A (4,16,D), B (4,4096,16)
// P = Xh*Wh + Xh*Wl + Xl*Wh  (fp32 accum)  -> rel_err ~1e-5
// Pipeline:
//   prepA : A_ext = [A(64); router_w(4); 0(8)] -> bf16 hi/lo u32, K-major
//   prepB : B -> Bf[o][er] bf16 hi/lo u32
//   mid   : midp[split] = x @ A_ext^T  (N=72: 4 tile-pairs + 1 single)
//   comb  : gates (top-2 softmax * 4.0, shfl-shared) + gmid -> bf16 hi/lo
//   out   : out = gmid @ Bf^T  (K=64 single shot)
// ---------------------------------------------------------------------------

#define D_DIM   4096
#define O_DIM   4096
#define MAXT    8192
#define LSCALE  4.0f
#define KSPLIT  4
#define NROWS   72            // 64 lora + 4 router + 4 pad (9 n-tiles)
#define NSMEM   80            // smem rows reserved (ldsm x2 lane-addr safety)
#define NSTORE  72
#define KU      (D_DIM / 2)   // u32 per A_ext row
#define S       72            // smem row stride in bf16 halves (144 B, 16B-mult)

// ------------------------- device scratch (static) -------------------------
__device__ float    g_midp[KSPLIT][MAXT][NSTORE];   // 9.4 MB
__device__ uint32_t g_Axh[NROWS][KU];               // 0.58 MB
__device__ uint32_t g_Axl[NROWS][KU];
__device__ uint32_t g_Bh[O_DIM][32];                // 0.5 MB
__device__ uint32_t g_Bl[O_DIM][32];
__device__ uint32_t g_Gh[MAXT][32];                 // 1 MB
__device__ uint32_t g_Gl[MAXT][32];

// ------------------------------ helpers ------------------------------------
static __device__ __forceinline__ uint32_t smem_u32(const void* p) {
    uint32_t a;
    asm("{ .reg .u64 t; cvta.to.shared.u64 t, %1; cvt.u32.u64 %0, t; }"
        : "=r"(a) : "l"(p));
    return a;
}
// fast split: hi = rn-bf16 pair (1 cvt), lo = rn-bf16 of exact residuals
static __device__ __forceinline__ void split2(float a, float b,
                                              uint32_t& hi, uint32_t& lo) {
    uint32_t h;
    asm("cvt.rn.bf16x2.f32 %0, %1, %2;" : "=r"(h) : "f"(b), "f"(a));
    float ahf = __uint_as_float(h << 16);
    float bhf = __uint_as_float(h & 0xFFFF0000u);
    float al = a - ahf;
    float bl = b - bhf;
    uint32_t l;
    asm("cvt.rn.bf16x2.f32 %0, %1, %2;" : "=r"(l) : "f"(bl), "f"(al));
    hi = h; lo = l;
}
static __device__ __forceinline__ void mma_bf16(float* c,
        uint32_t a0, uint32_t a1, uint32_t a2, uint32_t a3,
        uint32_t b0, uint32_t b1) {
    asm volatile(
        "mma.sync.aligned.m16n8k16.row.col.f32.bf16.bf16.f32 "
        "{%0,%1,%2,%3},{%4,%5,%6,%7},{%8,%9},{%0,%1,%2,%3};"
        : "+f"(c[0]), "+f"(c[1]), "+f"(c[2]), "+f"(c[3])
        : "r"(a0), "r"(a1), "r"(a2), "r"(a3), "r"(b0), "r"(b1));
}
#define LDSM_X4(d0, d1, d2, d3, a)                                           \
    asm volatile("ldmatrix.sync.aligned.m8n8.x4.shared.b16 {%0,%1,%2,%3}, [%4];" \
                 : "=r"(d0), "=r"(d1), "=r"(d2), "=r"(d3) : "r"(a))
#define LDSM_X2(d0, d1, a)                                                   \
    asm volatile("ldmatrix.sync.aligned.m8n8.x2.shared.b16 {%0,%1}, [%2];"   \
                 : "=r"(d0), "=r"(d1) : "r"(a))

// ---------------------------------------------------------------------------
// prepA: A_ext (72, 4096) -> hi/lo bf16 u32 pairs, K-major.
// ---------------------------------------------------------------------------
__global__ __launch_bounds__(256)
void prepA_kernel(const float* __restrict__ A, const float* __restrict__ rw)
{
    int idx = blockIdx.x * blockDim.x + threadIdx.x;   // NROWS * 1024 quads
    if (idx >= NROWS * 1024) return;
    int row = idx >> 10;
    int q   = idx & 1023;
    float4 v = make_float4(0.f, 0.f, 0.f, 0.f);
    if (row < 64)
        v = *reinterpret_cast<const float4*>(A + (size_t)row * D_DIM + q * 4);
    else if (row < 68)
        v = *reinterpret_cast<const float4*>(rw + (size_t)(row - 64) * D_DIM + q * 4);
    uint32_t h0, l0, h1, l1;
    split2(v.x, v.y, h0, l0);
    split2(v.z, v.w, h1, l1);
    *reinterpret_cast<uint2*>(&g_Axh[row][q * 2]) = make_uint2(h0, h1);
    *reinterpret_cast<uint2*>(&g_Axl[row][q * 2]) = make_uint2(l0, l1);
}

// ---------------------------------------------------------------------------
// prepB: B (E,O,R) -> Bf[o][er] bf16 hi/lo.
// ---------------------------------------------------------------------------
__global__ __launch_bounds__(256)
void prepB_kernel(const float* __restrict__ B)
{
    int o = blockIdx.x * blockDim.x + threadIdx.x;
    if (o >= O_DIM) return;
    #pragma unroll
    for (int e = 0; e < 4; e++) {
        const float4* src = reinterpret_cast<const float4*>(
            B + ((size_t)e * O_DIM + o) * 16);
        #pragma unroll
        for (int i = 0; i < 4; i++) {
            float4 v = src[i];
            uint32_t h0, l0, h1, l1;
            split2(v.x, v.y, h0, l0);
            split2(v.z, v.w, h1, l1);
            *reinterpret_cast<uint2*>(&g_Bh[o][e * 8 + i * 2]) = make_uint2(h0, h1);
            *reinterpret_cast<uint2*>(&g_Bl[o][e * 8 + i * 2]) = make_uint2(l0, l1);
        }
    }
}

// ---------------------------------------------------------------------------
// mid: midp[split] = x @ A_ext^T.  grid (T/128, KSPLIT), 256 thr.
//   smem: xh|xl (128 x S) + ah|al (NSMEM x S) -> 58.5 KB, 2 CTAs/SM.
// ---------------------------------------------------------------------------
#define MID_DSM ((2 * 128 + 2 * NSMEM) * S * 2)

__global__ __launch_bounds__(256, 2)
void mid_kernel(const float* __restrict__ x)
{
    extern __shared__ __align__(16) uint16_t sm_mid[];
    const uint32_t base = smem_u32(sm_mid);
    uint32_t* xh32 = reinterpret_cast<uint32_t*>(sm_mid);
    uint32_t* xl32 = xh32 + 128 * (S / 2);
    uint32_t* ah32 = xl32 + 128 * (S / 2);
    uint32_t* al32 = ah32 + NSMEM * (S / 2);
    const uint32_t xh_b = base;
    const uint32_t xl_b = base + 128 * S * 2;
    const uint32_t ah_b = base + 256 * S * 2;
    const uint32_t al_b = base + (256 + NSMEM) * S * 2;

    const int tid  = threadIdx.x;
    const int w    = tid >> 5;
    const int lane = tid & 31;
    const int g    = lane >> 2;
    const int tig  = lane & 3;
    const int t0   = blockIdx.x * 128;
    const int split = blockIdx.y;
    const int kbase = split * (D_DIM / KSPLIT);

    // ldmatrix per-lane address components
    const int arow = (lane & 7) + ((lane >> 3) & 1) * 8;   // A-frag (x tile)
    const int acol = (lane >> 4) * 8;
    const int brow = (lane & 7) + (lane >> 4) * 8;         // B-frag (A_ext tile)
    const int bcol = ((lane >> 3) & 1) * 8;
    const int brow2 = 64 + (lane & 7);                     // single-tile x2 rows
    const int bcol2 = ((lane >> 3) & 1) * 8;
    const uint32_t axh = xh_b + (uint32_t)(((w * 16 + arow) * S + acol) * 2);
    const uint32_t axl = xl_b + (uint32_t)(((w * 16 + arow) * S + acol) * 2);
    const uint32_t bah = ah_b + (uint32_t)((brow * S + bcol) * 2);
    const uint32_t bal = al_b + (uint32_t)((brow * S + bcol) * 2);
    const uint32_t bah2 = ah_b + (uint32_t)((brow2 * S + bcol2) * 2);
    const uint32_t bal2 = al_b + (uint32_t)((brow2 * S + bcol2) * 2);

    // staging index precompute
    const int xr = tid >> 4, xq = tid & 15;       // x: row, float4-col
    const int ar = tid >> 5, aj = tid & 31;       // A: row base, u32-col

    float acc[9][4] = {};

    for (int c = 0; c < (D_DIM / KSPLIT) / 64; c++) {   // 16 chunks
        const int k0  = kbase + c * 64;
        const int kq0 = k0 >> 1;

        // issue global loads into registers (overlaps with sync wait)
        float4 xv[8];
        #pragma unroll
        for (int p = 0; p < 8; p++)
            xv[p] = *reinterpret_cast<const float4*>(
                x + (size_t)(t0 + xr + p * 16) * D_DIM + k0 + xq * 4);
        uint32_t avh[9], avl[9];
        #pragma unroll
        for (int p = 0; p < 9; p++) {
            int row = ar + p * 8;
            avh[p] = g_Axh[row][kq0 + aj];
            avl[p] = g_Axl[row][kq0 + aj];
        }

        __syncthreads();   // prior chunk's compute done reading smem

        #pragma unroll
        for (int p = 0; p < 8; p++) {
            uint32_t h0, l0, h1, l1;
            split2(xv[p].x, xv[p].y, h0, l0);
            split2(xv[p].z, xv[p].w, h1, l1);
            int u = (xr + p * 16) * (S / 2) + xq * 2;
            *reinterpret_cast<uint2*>(&xh32[u]) = make_uint2(h0, h1);
            *reinterpret_cast<uint2*>(&xl32[u]) = make_uint2(l0, l1);
        }
        #pragma unroll
        for (int p = 0; p < 9; p++) {
            int u = (ar + p * 8) * (S / 2) + aj;
            ah32[u] = avh[p];
            al32[u] = avl[p];
        }
        __syncthreads();

        #pragma unroll
        for (int ks = 0; ks < 4; ks++) {
            const uint32_t kb = (uint32_t)(ks * 32);   // 16 halves
            uint32_t ah0, ah1, ah2, ah3, al0, al1, al2, al3;
            LDSM_X4(ah0, ah1, ah2, ah3, axh + kb);
            LDSM_X4(al0, al1, al2, al3, axl + kb);
            #pragma unroll
            for (int ntp = 0; ntp < 4; ntp++) {        // tile pairs 0..7
                const uint32_t bo = (uint32_t)(ntp * 16 * S * 2) + kb;
                uint32_t bh0, bh1, bh2, bh3, bl0, bl1, bl2, bl3;
                LDSM_X4(bh0, bh1, bh2, bh3, bah + bo);
                LDSM_X4(bl0, bl1, bl2, bl3, bal + bo);
                mma_bf16(acc[2 * ntp],     ah0, ah1, ah2, ah3, bh0, bh1);
                mma_bf16(acc[2 * ntp],     ah0, ah1, ah2, ah3, bl0, bl1);
                mma_bf16(acc[2 * ntp],     al0, al1, al2, al3, bh0, bh1);
                mma_bf16(acc[2 * ntp + 1], ah0, ah1, ah2, ah3, bh2, bh3);
                mma_bf16(acc[2 * ntp + 1], ah0, ah1, ah2, ah3, bl2, bl3);
                mma_bf16(acc[2 * ntp + 1], al0, al1, al2, al3, bh2, bh3);
            }
            {   // single tile 8 (cols 64..71, incl. router logits)
                uint32_t bh0, bh1, bl0, bl1;
                LDSM_X2(bh0, bh1, bah2 + kb);
                LDSM_X2(bl0, bl1, bal2 + kb);
                mma_bf16(acc[8], ah0, ah1, ah2, ah3, bh0, bh1);
                mma_bf16(acc[8], ah0, ah1, ah2, ah3, bl0, bl1);
                mma_bf16(acc[8], al0, al1, al2, al3, bh0, bh1);
            }
        }
    }

    const int r0 = t0 + w * 16 + g;
    #pragma unroll
    for (int nt = 0; nt < 9; nt++) {
        int col = nt * 8 + 2 * tig;
        *reinterpret_cast<float2*>(&g_midp[split][r0][col]) =
            make_float2(acc[nt][0], acc[nt][1]);
        *reinterpret_cast<float2*>(&g_midp[split][r0 + 8][col]) =
            make_float2(acc[nt][2], acc[nt][3]);
    }
}

// ---------------------------------------------------------------------------
// comb: gates (one lane per token + shfl broadcast) + gmid -> bf16 hi/lo.
// ---------------------------------------------------------------------------
__global__ __launch_bounds__(256)
void comb_kernel(int T)
{
    int idx = blockIdx.x * blockDim.x + threadIdx.x;
    if (idx >= T * 16) return;
    int t = idx >> 4;
    int j = idx & 15;
    int lane = threadIdx.x & 31;

    float g1 = 0.f, g2 = 0.f;
    int i1 = 0, i2 = 0;
    if ((lane & 15) == 0) {
        float l[4];
        #pragma unroll
        for (int e = 0; e < 4; e++) {
            float s = 0.f;
            #pragma unroll
            for (int p = 0; p < KSPLIT; p++) s += g_midp[p][t][64 + e];
            l[e] = s;
        }
        i1 = 0; float v1 = l[0];
        if (l[1] > v1) { v1 = l[1]; i1 = 1; }
        if (l[2] > v1) { v1 = l[2]; i1 = 2; }
        if (l[3] > v1) { v1 = l[3]; i1 = 3; }
        float v2 = -3.4e38f;
        #pragma unroll
        for (int e = 0; e < 4; e++)
            if (e != i1 && l[e] > v2) { v2 = l[e]; i2 = e; }
        float e2  = __expf(v2 - v1);
        float inv = 1.0f / (1.0f + e2);
        g1 = LSCALE * inv;
        g2 = LSCALE * e2 * inv;
    }
    const int src = lane & 16;
    i1 = __shfl_sync(0xffffffffu, i1, src);
    i2 = __shfl_sync(0xffffffffu, i2, src);
    g1 = __shfl_sync(0xffffffffu, g1, src);
    g2 = __shfl_sync(0xffffffffu, g2, src);

    int e_mine = j >> 2;
    float gv = (e_mine == i1) ? g1 : (e_mine == i2) ? g2 : 0.f;

    float4 s = make_float4(0.f, 0.f, 0.f, 0.f);
    #pragma unroll
    for (int p = 0; p < KSPLIT; p++) {
        float4 m = *reinterpret_cast<const float4*>(&g_midp[p][t][j * 4]);
        s.x += m.x; s.y += m.y; s.z += m.z; s.w += m.w;
    }
    uint32_t h0, l0, h1, l1;
    split2(s.x * gv, s.y * gv, h0, l0);
    split2(s.z * gv, s.w * gv, h1, l1);
    *reinterpret_cast<uint2*>(&g_Gh[t][j * 2]) = make_uint2(h0, h1);
    *reinterpret_cast<uint2*>(&g_Gl[t][j * 2]) = make_uint2(l0, l1);
}

// ---------------------------------------------------------------------------
// out: out = gmid @ Bf^T, 128x128 tile, K=64 single shot.
//   smem: gh|gl|bh|bl (each 128 x S) = 72 KB.  grid (O/128, T/128), 256 thr.
// ---------------------------------------------------------------------------
#define OUT_DSM (4 * 128 * S * 2)

__global__ __launch_bounds__(256, 2)
void out_kernel(float* __restrict__ out)
{
    extern __shared__ __align__(16) uint16_t sm_out[];
    const uint32_t base = smem_u32(sm_out);
    uint32_t* gh32 = reinterpret_cast<uint32_t*>(sm_out);
    uint32_t* gl32 = gh32 + 128 * (S / 2);
    uint32_t* bh32 = gl32 + 128 * (S / 2);
    uint32_t* bl32 = bh32 + 128 * (S / 2);
    const uint32_t gh_b = base;
    const uint32_t gl_b = base + 128 * S * 2;
    const uint32_t bh_b = base + 256 * S * 2;
    const uint32_t bl_b = base + 384 * S * 2;

    const int tid  = threadIdx.x;
    const int w    = tid >> 5;
    const int lane = tid & 31;
    const int g    = lane >> 2;
    const int tig  = lane & 3;
    const int n0   = blockIdx.x * 128;
    const int t0   = blockIdx.y * 128;

    // stage all four tiles (coalesced 128B rows)
    {
        const int r = tid >> 5, j = tid & 31;
        #pragma unroll
        for (int p = 0; p < 16; p++) {
            int row = r + p * 8;
            int u = row * (S / 2) + j;
            gh32[u] = g_Gh[t0 + row][j];
            gl32[u] = g_Gl[t0 + row][j];
            bh32[u] = g_Bh[n0 + row][j];
            bl32[u] = g_Bl[n0 + row][j];
        }
    }
    __syncthreads();

    const int arow = (lane & 7) + ((lane >> 3) & 1) * 8;
    const int acol = (lane >> 4) * 8;
    const int brow = (lane & 7) + (lane >> 4) * 8;
    const int bcol = ((lane >> 3) & 1) * 8;
    const uint32_t agh = gh_b + (uint32_t)(((w * 16 + arow) * S + acol) * 2);
    const uint32_t agl = gl_b + (uint32_t)(((w * 16 + arow) * S + acol) * 2);
    const uint32_t bbh = bh_b + (uint32_t)((brow * S + bcol) * 2);
    const uint32_t bbl = bl_b + (uint32_t)((brow * S + bcol) * 2);

    float acc[16][4] = {};

    #pragma unroll
    for (int ks = 0; ks < 4; ks++) {
        const uint32_t kb = (uint32_t)(ks * 32);
        uint32_t ah0, ah1, ah2, ah3, al0, al1, al2, al3;
        LDSM_X4(ah0, ah1, ah2, ah3, agh + kb);
        LDSM_X4(al0, al1, al2, al3, agl + kb);
        #pragma unroll
        for (int ntp = 0; ntp < 8; ntp++) {
            const uint32_t bo = (uint32_t)(ntp * 16 * S * 2) + kb;
            uint32_t bh0, bh1, bh2, bh3, bl0, bl1, bl2, bl3;
            LDSM_X4(bh0, bh1, bh2, bh3, bbh + bo);
            LDSM_X4(bl0, bl1, bl2, bl3, bbl + bo);
            mma_bf16(acc[2 * ntp],     ah0, ah1, ah2, ah3, bh0, bh1);
            mma_bf16(acc[2 * ntp],     ah0, ah1, ah2, ah3, bl0, bl1);
            mma_bf16(acc[2 * ntp],     al0, al1, al2, al3, bh0, bh1);
            mma_bf16(acc[2 * ntp + 1], ah0, ah1, ah2, ah3, bh2, bh3);
            mma_bf16(acc[2 * ntp + 1], ah0, ah1, ah2, ah3, bl2, bl3);
            mma_bf16(acc[2 * ntp + 1], al0, al1, al2, al3, bh2, bh3);
        }
    }

    const int r0 = t0 + w * 16 + g;
    #pragma unroll
    for (int nt = 0; nt < 16; nt++) {
        int col = n0 + nt * 8 + 2 * tig;
        *reinterpret_cast<float2*>(out + (size_t)r0 * O_DIM + col) =
            make_float2(acc[nt][0], acc[nt][1]);
        *reinterpret_cast<float2*>(out + (size_t)(r0 + 8) * O_DIM + col) =
            make_float2(acc[nt][2], acc[nt][3]);
    }
}

// ---------------------------------------------------------------------------
// launch
// ---------------------------------------------------------------------------
extern "C" void kernel_launch(void* const* d_in, const int* in_sizes, int n_in,
                              void* d_out, int out_size)
{
    const float* x  = (const float*)d_in[0];   // (T, D)
    const float* rw = (const float*)d_in[1];   // (E, D)
    const float* A  = (const float*)d_in[2];   // (E, R, D) == (64, D)
    const float* B  = (const float*)d_in[3];   // (E, O, R)
    float* out = (float*)d_out;                // (T, O)

    int T = in_sizes[0] / D_DIM;               // 8192

    cudaFuncSetAttribute(mid_kernel, cudaFuncAttributeMaxDynamicSharedMemorySize, MID_DSM);
    cudaFuncSetAttribute(out_kernel, cudaFuncAttributeMaxDynamicSharedMemorySize, OUT_DSM);

    prepA_kernel<<<(NROWS * 1024 + 255) / 256, 256>>>(A, rw);
    prepB_kernel<<<(O_DIM + 255) / 256, 256>>>(B);
    mid_kernel<<<dim3(T / 128, KSPLIT), 256, MID_DSM>>>(x);
    comb_kernel<<<(T * 16 + 255) / 256, 256>>>(T);
    out_kernel<<<dim3(O_DIM / 128, T / 128), 256, OUT_DSM>>>(out);
}

// round 10
// speedup vs baseline: 3.4483x; 1.0342x over previous
#include <cuda_runtime.h>
#include <cuda_bf16.h>
#include <cstdint>

// ---------------------------------------------------------------------------
// MoE LoRA delta via mma.sync bf16 hi/lo split, smem-staged ldmatrix feeds.
//   x (T=8192, D=4096) f32, router_w (4, D), A (4,16,D), B (4,4096,16)
// P = Xh*Wh + Xh*Wl + Xl*Wh  (fp32 accum)  -> rel_err ~1e-5
// Pipeline:
//   prep  : A_ext = [A(64); router_w(4); 0(8)] + B -> bf16 hi/lo u32 (merged)
//   mid   : midp[split] = x @ A_ext^T  (sw-pipelined LDG + cp.async dbl-buf A)
//   comb  : gates (top-2 softmax * 4.0, shfl-shared) + gmid -> bf16 hi/lo
//   out   : out = gmid @ Bf^T  (K=64 single shot, uint4 staging)
// ---------------------------------------------------------------------------

#define D_DIM   4096
#define O_DIM   4096
#define MAXT    8192
#define LSCALE  4.0f
#define KSPLIT  4
#define NROWS   72            // 64 lora + 4 router + 4 pad (9 n-tiles)
#define KU      (D_DIM / 2)   // u32 per A_ext row
#define S       72            // smem row stride in bf16 halves (144 B)

// ------------------------- device scratch (static) -------------------------
__device__ float    g_midp[KSPLIT][MAXT][NROWS];    // 9.4 MB
__device__ uint32_t g_Axh[NROWS][KU];               // 0.58 MB
__device__ uint32_t g_Axl[NROWS][KU];
__device__ uint32_t g_Bh[O_DIM][32];                // 0.5 MB
__device__ uint32_t g_Bl[O_DIM][32];
__device__ uint32_t g_Gh[MAXT][32];                 // 1 MB
__device__ uint32_t g_Gl[MAXT][32];

// ------------------------------ helpers ------------------------------------
static __device__ __forceinline__ uint32_t smem_u32(const void* p) {
    uint32_t a;
    asm("{ .reg .u64 t; cvta.to.shared.u64 t, %1; cvt.u32.u64 %0, t; }"
        : "=r"(a) : "l"(p));
    return a;
}
// fast split: hi = rn-bf16 pair (1 cvt), lo = rn-bf16 of exact residuals
static __device__ __forceinline__ void split2(float a, float b,
                                              uint32_t& hi, uint32_t& lo) {
    uint32_t h;
    asm("cvt.rn.bf16x2.f32 %0, %1, %2;" : "=r"(h) : "f"(b), "f"(a));
    float ahf = __uint_as_float(h << 16);
    float bhf = __uint_as_float(h & 0xFFFF0000u);
    float al = a - ahf;
    float bl = b - bhf;
    uint32_t l;
    asm("cvt.rn.bf16x2.f32 %0, %1, %2;" : "=r"(l) : "f"(bl), "f"(al));
    hi = h; lo = l;
}
static __device__ __forceinline__ void mma_bf16(float* c,
        uint32_t a0, uint32_t a1, uint32_t a2, uint32_t a3,
        uint32_t b0, uint32_t b1) {
    asm volatile(
        "mma.sync.aligned.m16n8k16.row.col.f32.bf16.bf16.f32 "
        "{%0,%1,%2,%3},{%4,%5,%6,%7},{%8,%9},{%0,%1,%2,%3};"
        : "+f"(c[0]), "+f"(c[1]), "+f"(c[2]), "+f"(c[3])
        : "r"(a0), "r"(a1), "r"(a2), "r"(a3), "r"(b0), "r"(b1));
}
#define LDSM_X4(d0, d1, d2, d3, a)                                           \
    asm volatile("ldmatrix.sync.aligned.m8n8.x4.shared.b16 {%0,%1,%2,%3}, [%4];" \
                 : "=r"(d0), "=r"(d1), "=r"(d2), "=r"(d3) : "r"(a))
#define LDSM_X2(d0, d1, a)                                                   \
    asm volatile("ldmatrix.sync.aligned.m8n8.x2.shared.b16 {%0,%1}, [%2];"   \
                 : "=r"(d0), "=r"(d1) : "r"(a))
#define CP_ASYNC16(dst, src)                                                 \
    asm volatile("cp.async.cg.shared.global [%0], [%1], 16;"                 \
                 :: "r"(dst), "l"(src) : "memory")
#define CP_COMMIT() asm volatile("cp.async.commit_group;" ::: "memory")
#define CP_WAIT1()  asm volatile("cp.async.wait_group 1;" ::: "memory")
#define CP_WAIT0()  asm volatile("cp.async.wait_group 0;" ::: "memory")

// ---------------------------------------------------------------------------
// prep (merged): blocks [0,288): A_ext -> g_Ax{h,l};  [288,304): B -> g_B{h,l}
// ---------------------------------------------------------------------------
__global__ __launch_bounds__(256)
void prep_kernel(const float* __restrict__ A, const float* __restrict__ rw,
                 const float* __restrict__ B)
{
    int bid = blockIdx.x;
    if (bid < 288) {
        int idx = bid * 256 + threadIdx.x;     // < NROWS * 1024
        int row = idx >> 10;
        int q   = idx & 1023;
        float4 v = make_float4(0.f, 0.f, 0.f, 0.f);
        if (row < 64)
            v = *reinterpret_cast<const float4*>(A + (size_t)row * D_DIM + q * 4);
        else if (row < 68)
            v = *reinterpret_cast<const float4*>(rw + (size_t)(row - 64) * D_DIM + q * 4);
        uint32_t h0, l0, h1, l1;
        split2(v.x, v.y, h0, l0);
        split2(v.z, v.w, h1, l1);
        *reinterpret_cast<uint2*>(&g_Axh[row][q * 2]) = make_uint2(h0, h1);
        *reinterpret_cast<uint2*>(&g_Axl[row][q * 2]) = make_uint2(l0, l1);
    } else {
        int o = (bid - 288) * 256 + threadIdx.x;
        if (o >= O_DIM) return;
        #pragma unroll
        for (int e = 0; e < 4; e++) {
            const float4* src = reinterpret_cast<const float4*>(
                B + ((size_t)e * O_DIM + o) * 16);
            #pragma unroll
            for (int i = 0; i < 4; i++) {
                float4 v = src[i];
                uint32_t h0, l0, h1, l1;
                split2(v.x, v.y, h0, l0);
                split2(v.z, v.w, h1, l1);
                *reinterpret_cast<uint2*>(&g_Bh[o][e * 8 + i * 2]) = make_uint2(h0, h1);
                *reinterpret_cast<uint2*>(&g_Bl[o][e * 8 + i * 2]) = make_uint2(l0, l1);
            }
        }
    }
}

// ---------------------------------------------------------------------------
// mid: midp[split] = x @ A_ext^T.  grid (T/128, KSPLIT), 256 thr.
//   x: LDG->reg for chunk c+1 issued before compute(c) (latency hidden).
//   A: cp.async into double-buffered smem (wait_group 1 keeps 1 in flight).
//   smem: xh|xl (128 x S) + 2 x (ah|al) (80 x S) = 82,944 B; 2 CTAs/SM.
// ---------------------------------------------------------------------------
#define AROWS_SM   80
#define ABUF_BYTES (2 * AROWS_SM * S * 2)           // hi+lo per buffer: 23,040
#define MID_DSM    (2 * 128 * S * 2 + 2 * ABUF_BYTES)   // 82,944

__global__ __launch_bounds__(256, 2)
void mid_kernel(const float* __restrict__ x)
{
    extern __shared__ __align__(16) uint16_t sm_mid[];
    const uint32_t base = smem_u32(sm_mid);
    uint32_t* xh32 = reinterpret_cast<uint32_t*>(sm_mid);
    uint32_t* xl32 = xh32 + 128 * (S / 2);
    const uint32_t xh_b = base;
    const uint32_t xl_b = base + 128 * S * 2;
    const uint32_t a0_b = base + 256 * S * 2;       // buf0 hi; lo at +AROWS_SM*S*2

    const int tid  = threadIdx.x;
    const int w    = tid >> 5;
    const int lane = tid & 31;
    const int g    = lane >> 2;
    const int tig  = lane & 3;
    const int t0   = blockIdx.x * 128;
    const int split = blockIdx.y;
    const int kbase = split * (D_DIM / KSPLIT);

    // ldmatrix per-lane address components
    const int arow = (lane & 7) + ((lane >> 3) & 1) * 8;   // A-frag (x tile)
    const int acol = (lane >> 4) * 8;
    const int brow = (lane & 7) + (lane >> 4) * 8;         // B-frag (A_ext tile)
    const int bcol = ((lane >> 3) & 1) * 8;
    const int brow2 = 64 + (lane & 7);                     // single-tile x2 rows
    const int bcol2 = ((lane >> 3) & 1) * 8;
    const uint32_t axh = xh_b + (uint32_t)(((w * 16 + arow) * S + acol) * 2);
    const uint32_t axl = xl_b + (uint32_t)(((w * 16 + arow) * S + acol) * 2);
    const uint32_t bah  = a0_b + (uint32_t)((brow * S + bcol) * 2);
    const uint32_t bal  = a0_b + (uint32_t)(AROWS_SM * S * 2 + (brow * S + bcol) * 2);
    const uint32_t bah2 = a0_b + (uint32_t)((brow2 * S + bcol2) * 2);
    const uint32_t bal2 = a0_b + (uint32_t)(AROWS_SM * S * 2 + (brow2 * S + bcol2) * 2);

    // staging indices
    const int xr = tid >> 4, xq = tid & 15;       // x: row, float4-col

    // A cp.async op map: 1152 = 2(hl) * 72 rows * 8 uint4-cols
    int cp_hl[5], cp_row[5], cp_c4[5];
    bool cp_on[5];
    #pragma unroll
    for (int p = 0; p < 5; p++) {
        int idx = tid + p * 256;
        cp_on[p] = idx < 1152;
        int hl = idx >= 576 ? 1 : 0;
        int r2 = idx - hl * 576;
        cp_hl[p] = hl;
        cp_row[p] = r2 >> 3;
        cp_c4[p] = r2 & 7;
    }

    const int NCHUNK = (D_DIM / KSPLIT) / 64;     // 16

    // prologue: A(0) cp.async into buf0; x(0) LDG into regs
    {
        const int kq = kbase >> 1;
        #pragma unroll
        for (int p = 0; p < 5; p++) {
            if (cp_on[p]) {
                const uint32_t* src = (cp_hl[p] ? g_Axl[cp_row[p]] : g_Axh[cp_row[p]])
                                      + kq + cp_c4[p] * 4;
                uint32_t dst = a0_b + (uint32_t)(cp_hl[p] * (AROWS_SM * S * 2)
                             + cp_row[p] * (S * 2) + cp_c4[p] * 16);
                CP_ASYNC16(dst, src);
            }
        }
        CP_COMMIT();
    }
    float4 xv[8];
    #pragma unroll
    for (int p = 0; p < 8; p++)
        xv[p] = *reinterpret_cast<const float4*>(
            x + (size_t)(t0 + xr + p * 16) * D_DIM + kbase + xq * 4);

    float acc[9][4] = {};

    for (int c = 0; c < NCHUNK; c++) {
        __syncthreads();   // compute(c-1) done reading x smem & A buf[(c+1)&1]

        // STS x(c) from regs
        #pragma unroll
        for (int p = 0; p < 8; p++) {
            uint32_t h0, l0, h1, l1;
            split2(xv[p].x, xv[p].y, h0, l0);
            split2(xv[p].z, xv[p].w, h1, l1);
            int u = (xr + p * 16) * (S / 2) + xq * 2;
            *reinterpret_cast<uint2*>(&xh32[u]) = make_uint2(h0, h1);
            *reinterpret_cast<uint2*>(&xl32[u]) = make_uint2(l0, l1);
        }

        if (c + 1 < NCHUNK) {
            // issue A(c+1) cp.async into buf[(c+1)&1]
            const int kq = (kbase + (c + 1) * 64) >> 1;
            const uint32_t bufo = (uint32_t)(((c + 1) & 1) * ABUF_BYTES);
            #pragma unroll
            for (int p = 0; p < 5; p++) {
                if (cp_on[p]) {
                    const uint32_t* src = (cp_hl[p] ? g_Axl[cp_row[p]] : g_Axh[cp_row[p]])
                                          + kq + cp_c4[p] * 4;
                    uint32_t dst = a0_b + bufo + (uint32_t)(cp_hl[p] * (AROWS_SM * S * 2)
                                 + cp_row[p] * (S * 2) + cp_c4[p] * 16);
                    CP_ASYNC16(dst, src);
                }
            }
            CP_COMMIT();
            // issue x(c+1) LDG into regs (latency overlaps compute(c))
            const int k1 = kbase + (c + 1) * 64;
            #pragma unroll
            for (int p = 0; p < 8; p++)
                xv[p] = *reinterpret_cast<const float4*>(
                    x + (size_t)(t0 + xr + p * 16) * D_DIM + k1 + xq * 4);
            CP_WAIT1();   // A(c) complete; A(c+1) may stay in flight
        } else {
            CP_WAIT0();   // last chunk: A(c) complete
        }
        __syncthreads();

        const uint32_t aoff = (uint32_t)((c & 1) * ABUF_BYTES);
        #pragma unroll
        for (int ks = 0; ks < 4; ks++) {
            const uint32_t kb = (uint32_t)(ks * 32);   // 16 halves
            uint32_t ah0, ah1, ah2, ah3, al0, al1, al2, al3;
            LDSM_X4(ah0, ah1, ah2, ah3, axh + kb);
            LDSM_X4(al0, al1, al2, al3, axl + kb);
            #pragma unroll
            for (int ntp = 0; ntp < 4; ntp++) {        // tile pairs 0..7
                const uint32_t bo = (uint32_t)(ntp * 16 * S * 2) + kb + aoff;
                uint32_t bh0, bh1, bh2, bh3, bl0, bl1, bl2, bl3;
                LDSM_X4(bh0, bh1, bh2, bh3, bah + bo);
                LDSM_X4(bl0, bl1, bl2, bl3, bal + bo);
                mma_bf16(acc[2 * ntp],     ah0, ah1, ah2, ah3, bh0, bh1);
                mma_bf16(acc[2 * ntp],     ah0, ah1, ah2, ah3, bl0, bl1);
                mma_bf16(acc[2 * ntp],     al0, al1, al2, al3, bh0, bh1);
                mma_bf16(acc[2 * ntp + 1], ah0, ah1, ah2, ah3, bh2, bh3);
                mma_bf16(acc[2 * ntp + 1], ah0, ah1, ah2, ah3, bl2, bl3);
                mma_bf16(acc[2 * ntp + 1], al0, al1, al2, al3, bh2, bh3);
            }
            {   // single tile 8 (cols 64..71, incl. router logits)
                uint32_t bh0, bh1, bl0, bl1;
                LDSM_X2(bh0, bh1, bah2 + kb + aoff);
                LDSM_X2(bl0, bl1, bal2 + kb + aoff);
                mma_bf16(acc[8], ah0, ah1, ah2, ah3, bh0, bh1);
                mma_bf16(acc[8], ah0, ah1, ah2, ah3, bl0, bl1);
                mma_bf16(acc[8], al0, al1, al2, al3, bh0, bh1);
            }
        }
    }

    const int r0 = t0 + w * 16 + g;
    #pragma unroll
    for (int nt = 0; nt < 9; nt++) {
        int col = nt * 8 + 2 * tig;
        *reinterpret_cast<float2*>(&g_midp[split][r0][col]) =
            make_float2(acc[nt][0], acc[nt][1]);
        *reinterpret_cast<float2*>(&g_midp[split][r0 + 8][col]) =
            make_float2(acc[nt][2], acc[nt][3]);
    }
}

// ---------------------------------------------------------------------------
// comb: gates (one lane per token + shfl broadcast) + gmid -> bf16 hi/lo.
// ---------------------------------------------------------------------------
__global__ __launch_bounds__(256)
void comb_kernel(int T)
{
    int idx = blockIdx.x * blockDim.x + threadIdx.x;
    if (idx >= T * 16) return;
    int t = idx >> 4;
    int j = idx & 15;
    int lane = threadIdx.x & 31;

    float g1 = 0.f, g2 = 0.f;
    int i1 = 0, i2 = 0;
    if ((lane & 15) == 0) {
        float l[4];
        #pragma unroll
        for (int e = 0; e < 4; e++) {
            float s = 0.f;
            #pragma unroll
            for (int p = 0; p < KSPLIT; p++) s += g_midp[p][t][64 + e];
            l[e] = s;
        }
        i1 = 0; float v1 = l[0];
        if (l[1] > v1) { v1 = l[1]; i1 = 1; }
        if (l[2] > v1) { v1 = l[2]; i1 = 2; }
        if (l[3] > v1) { v1 = l[3]; i1 = 3; }
        float v2 = -3.4e38f;
        #pragma unroll
        for (int e = 0; e < 4; e++)
            if (e != i1 && l[e] > v2) { v2 = l[e]; i2 = e; }
        float e2  = __expf(v2 - v1);
        float inv = 1.0f / (1.0f + e2);
        g1 = LSCALE * inv;
        g2 = LSCALE * e2 * inv;
    }
    const int src = lane & 16;
    i1 = __shfl_sync(0xffffffffu, i1, src);
    i2 = __shfl_sync(0xffffffffu, i2, src);
    g1 = __shfl_sync(0xffffffffu, g1, src);
    g2 = __shfl_sync(0xffffffffu, g2, src);

    int e_mine = j >> 2;
    float gv = (e_mine == i1) ? g1 : (e_mine == i2) ? g2 : 0.f;

    float4 s = make_float4(0.f, 0.f, 0.f, 0.f);
    #pragma unroll
    for (int p = 0; p < KSPLIT; p++) {
        float4 m = *reinterpret_cast<const float4*>(&g_midp[p][t][j * 4]);
        s.x += m.x; s.y += m.y; s.z += m.z; s.w += m.w;
    }
    uint32_t h0, l0, h1, l1;
    split2(s.x * gv, s.y * gv, h0, l0);
    split2(s.z * gv, s.w * gv, h1, l1);
    *reinterpret_cast<uint2*>(&g_Gh[t][j * 2]) = make_uint2(h0, h1);
    *reinterpret_cast<uint2*>(&g_Gl[t][j * 2]) = make_uint2(l0, l1);
}

// ---------------------------------------------------------------------------
// out: out = gmid @ Bf^T, 128x128 tile, K=64 single shot, uint4 staging.
//   smem: gh|gl|bh|bl (each 128 x S) = 72 KB.  grid (O/128, T/128), 256 thr.
// ---------------------------------------------------------------------------
#define OUT_DSM (4 * 128 * S * 2)

__global__ __launch_bounds__(256, 2)
void out_kernel(float* __restrict__ out)
{
    extern __shared__ __align__(16) uint16_t sm_out[];
    const uint32_t base = smem_u32(sm_out);
    uint32_t* gh32 = reinterpret_cast<uint32_t*>(sm_out);
    uint32_t* gl32 = gh32 + 128 * (S / 2);
    uint32_t* bh32 = gl32 + 128 * (S / 2);
    uint32_t* bl32 = bh32 + 128 * (S / 2);
    const uint32_t gh_b = base;
    const uint32_t gl_b = base + 128 * S * 2;
    const uint32_t bh_b = base + 256 * S * 2;
    const uint32_t bl_b = base + 384 * S * 2;

    const int tid  = threadIdx.x;
    const int w    = tid >> 5;
    const int lane = tid & 31;
    const int g    = lane >> 2;
    const int tig  = lane & 3;
    const int n0   = blockIdx.x * 128;
    const int t0   = blockIdx.y * 128;

    // stage all four tiles via uint4 (16 LDG.128 + 16 STS.128 per thread)
    #pragma unroll
    for (int p = 0; p < 4; p++) {
        int idx = tid + p * 256;        // 0..1023
        int row = idx >> 3;
        int q   = idx & 7;
        int u   = row * (S / 2) + q * 4;
        *reinterpret_cast<uint4*>(&gh32[u]) =
            *reinterpret_cast<const uint4*>(&g_Gh[t0 + row][q * 4]);
        *reinterpret_cast<uint4*>(&gl32[u]) =
            *reinterpret_cast<const uint4*>(&g_Gl[t0 + row][q * 4]);
        *reinterpret_cast<uint4*>(&bh32[u]) =
            *reinterpret_cast<const uint4*>(&g_Bh[n0 + row][q * 4]);
        *reinterpret_cast<uint4*>(&bl32[u]) =
            *reinterpret_cast<const uint4*>(&g_Bl[n0 + row][q * 4]);
    }
    __syncthreads();

    const int arow = (lane & 7) + ((lane >> 3) & 1) * 8;
    const int acol = (lane >> 4) * 8;
    const int brow = (lane & 7) + (lane >> 4) * 8;
    const int bcol = ((lane >> 3) & 1) * 8;
    const uint32_t agh = gh_b + (uint32_t)(((w * 16 + arow) * S + acol) * 2);
    const uint32_t agl = gl_b + (uint32_t)(((w * 16 + arow) * S + acol) * 2);
    const uint32_t bbh = bh_b + (uint32_t)((brow * S + bcol) * 2);
    const uint32_t bbl = bl_b + (uint32_t)((brow * S + bcol) * 2);

    float acc[16][4] = {};

    #pragma unroll
    for (int ks = 0; ks < 4; ks++) {
        const uint32_t kb = (uint32_t)(ks * 32);
        uint32_t ah0, ah1, ah2, ah3, al0, al1, al2, al3;
        LDSM_X4(ah0, ah1, ah2, ah3, agh + kb);
        LDSM_X4(al0, al1, al2, al3, agl + kb);
        #pragma unroll
        for (int ntp = 0; ntp < 8; ntp++) {
            const uint32_t bo = (uint32_t)(ntp * 16 * S * 2) + kb;
            uint32_t bh0, bh1, bh2, bh3, bl0, bl1, bl2, bl3;
            LDSM_X4(bh0, bh1, bh2, bh3, bbh + bo);
            LDSM_X4(bl0, bl1, bl2, bl3, bbl + bo);
            mma_bf16(acc[2 * ntp],     ah0, ah1, ah2, ah3, bh0, bh1);
            mma_bf16(acc[2 * ntp],     ah0, ah1, ah2, ah3, bl0, bl1);
            mma_bf16(acc[2 * ntp],     al0, al1, al2, al3, bh0, bh1);
            mma_bf16(acc[2 * ntp + 1], ah0, ah1, ah2, ah3, bh2, bh3);
            mma_bf16(acc[2 * ntp + 1], ah0, ah1, ah2, ah3, bl2, bl3);
            mma_bf16(acc[2 * ntp + 1], al0, al1, al2, al3, bh2, bh3);
        }
    }

    const int r0 = t0 + w * 16 + g;
    #pragma unroll
    for (int nt = 0; nt < 16; nt++) {
        int col = n0 + nt * 8 + 2 * tig;
        *reinterpret_cast<float2*>(out + (size_t)r0 * O_DIM + col) =
            make_float2(acc[nt][0], acc[nt][1]);
        *reinterpret_cast<float2*>(out + (size_t)(r0 + 8) * O_DIM + col) =
            make_float2(acc[nt][2], acc[nt][3]);
    }
}

// ---------------------------------------------------------------------------
// launch
// ---------------------------------------------------------------------------
extern "C" void kernel_launch(void* const* d_in, const int* in_sizes, int n_in,
                              void* d_out, int out_size)
{
    const float* x  = (const float*)d_in[0];   // (T, D)
    const float* rw = (const float*)d_in[1];   // (E, D)
    const float* A  = (const float*)d_in[2];   // (E, R, D) == (64, D)
    const float* B  = (const float*)d_in[3];   // (E, O, R)
    float* out = (float*)d_out;                // (T, O)

    int T = in_sizes[0] / D_DIM;               // 8192

    cudaFuncSetAttribute(mid_kernel, cudaFuncAttributeMaxDynamicSharedMemorySize, MID_DSM);
    cudaFuncSetAttribute(out_kernel, cudaFuncAttributeMaxDynamicSharedMemorySize, OUT_DSM);

    prep_kernel<<<288 + 16, 256>>>(A, rw, B);
    mid_kernel<<<dim3(T / 128, KSPLIT), 256, MID_DSM>>>(x);
    comb_kernel<<<(T * 16 + 255) / 256, 256>>>(T);
    out_kernel<<<dim3(O_DIM / 128, T / 128), 256, OUT_DSM>>>(out);
}

// round 11
// speedup vs baseline: 3.4896x; 1.0120x over previous
#include <cuda_runtime.h>
#include <cuda_bf16.h>
#include <cstdint>

// ---------------------------------------------------------------------------
// MoE LoRA delta via mma.sync bf16 hi/lo split, smem-staged ldmatrix feeds.
//   x (T=8192, D=4096) f32, router_w (4, D), A (4,16,D), B (4,4096,16)
// P = Xh*Wh + Xh*Wl + Xl*Wh  (fp32 accum)  -> rel_err ~1e-5
// Pipeline:
//   prep  : A_ext = [A(64); router_w(4); 0(8)] + B -> bf16 hi/lo u32 (merged)
//   mid   : midp[split] = x @ A_ext^T  (sw-pipelined LDG + cp.async dbl-buf A)
//   comb  : gates (top-2 softmax * 4.0, shfl-shared) + gmid -> bf16 hi/lo
//   out   : out = gmid @ Bf^T  (K=64, 4x2 warp grid: 32x64 per warp)
// ---------------------------------------------------------------------------

#define D_DIM   4096
#define O_DIM   4096
#define MAXT    8192
#define LSCALE  4.0f
#define KSPLIT  4
#define NROWS   72            // 64 lora + 4 router + 4 pad (9 n-tiles)
#define KU      (D_DIM / 2)   // u32 per A_ext row
#define S       72            // smem row stride in bf16 halves (144 B)

// ------------------------- device scratch (static) -------------------------
__device__ float    g_midp[KSPLIT][MAXT][NROWS];    // 9.4 MB
__device__ uint32_t g_Axh[NROWS][KU];               // 0.58 MB
__device__ uint32_t g_Axl[NROWS][KU];
__device__ uint32_t g_Bh[O_DIM][32];                // 0.5 MB
__device__ uint32_t g_Bl[O_DIM][32];
__device__ uint32_t g_Gh[MAXT][32];                 // 1 MB
__device__ uint32_t g_Gl[MAXT][32];

// ------------------------------ helpers ------------------------------------
static __device__ __forceinline__ uint32_t smem_u32(const void* p) {
    uint32_t a;
    asm("{ .reg .u64 t; cvta.to.shared.u64 t, %1; cvt.u32.u64 %0, t; }"
        : "=r"(a) : "l"(p));
    return a;
}
// fast split: hi = rn-bf16 pair (1 cvt), lo = rn-bf16 of exact residuals
static __device__ __forceinline__ void split2(float a, float b,
                                              uint32_t& hi, uint32_t& lo) {
    uint32_t h;
    asm("cvt.rn.bf16x2.f32 %0, %1, %2;" : "=r"(h) : "f"(b), "f"(a));
    float ahf = __uint_as_float(h << 16);
    float bhf = __uint_as_float(h & 0xFFFF0000u);
    float al = a - ahf;
    float bl = b - bhf;
    uint32_t l;
    asm("cvt.rn.bf16x2.f32 %0, %1, %2;" : "=r"(l) : "f"(bl), "f"(al));
    hi = h; lo = l;
}
static __device__ __forceinline__ void mma_bf16(float* c,
        uint32_t a0, uint32_t a1, uint32_t a2, uint32_t a3,
        uint32_t b0, uint32_t b1) {
    asm volatile(
        "mma.sync.aligned.m16n8k16.row.col.f32.bf16.bf16.f32 "
        "{%0,%1,%2,%3},{%4,%5,%6,%7},{%8,%9},{%0,%1,%2,%3};"
        : "+f"(c[0]), "+f"(c[1]), "+f"(c[2]), "+f"(c[3])
        : "r"(a0), "r"(a1), "r"(a2), "r"(a3), "r"(b0), "r"(b1));
}
#define LDSM_X4(d0, d1, d2, d3, a)                                           \
    asm volatile("ldmatrix.sync.aligned.m8n8.x4.shared.b16 {%0,%1,%2,%3}, [%4];" \
                 : "=r"(d0), "=r"(d1), "=r"(d2), "=r"(d3) : "r"(a))
#define LDSM_X2(d0, d1, a)                                                   \
    asm volatile("ldmatrix.sync.aligned.m8n8.x2.shared.b16 {%0,%1}, [%2];"   \
                 : "=r"(d0), "=r"(d1) : "r"(a))
#define CP_ASYNC16(dst, src)                                                 \
    asm volatile("cp.async.cg.shared.global [%0], [%1], 16;"                 \
                 :: "r"(dst), "l"(src) : "memory")
#define CP_COMMIT() asm volatile("cp.async.commit_group;" ::: "memory")
#define CP_WAIT1()  asm volatile("cp.async.wait_group 1;" ::: "memory")
#define CP_WAIT0()  asm volatile("cp.async.wait_group 0;" ::: "memory")

// ---------------------------------------------------------------------------
// prep (merged): blocks [0,288): A_ext -> g_Ax{h,l};  [288,304): B -> g_B{h,l}
// ---------------------------------------------------------------------------
__global__ __launch_bounds__(256)
void prep_kernel(const float* __restrict__ A, const float* __restrict__ rw,
                 const float* __restrict__ B)
{
    int bid = blockIdx.x;
    if (bid < 288) {
        int idx = bid * 256 + threadIdx.x;     // < NROWS * 1024
        int row = idx >> 10;
        int q   = idx & 1023;
        float4 v = make_float4(0.f, 0.f, 0.f, 0.f);
        if (row < 64)
            v = *reinterpret_cast<const float4*>(A + (size_t)row * D_DIM + q * 4);
        else if (row < 68)
            v = *reinterpret_cast<const float4*>(rw + (size_t)(row - 64) * D_DIM + q * 4);
        uint32_t h0, l0, h1, l1;
        split2(v.x, v.y, h0, l0);
        split2(v.z, v.w, h1, l1);
        *reinterpret_cast<uint2*>(&g_Axh[row][q * 2]) = make_uint2(h0, h1);
        *reinterpret_cast<uint2*>(&g_Axl[row][q * 2]) = make_uint2(l0, l1);
    } else {
        int o = (bid - 288) * 256 + threadIdx.x;
        if (o >= O_DIM) return;
        #pragma unroll
        for (int e = 0; e < 4; e++) {
            const float4* src = reinterpret_cast<const float4*>(
                B + ((size_t)e * O_DIM + o) * 16);
            #pragma unroll
            for (int i = 0; i < 4; i++) {
                float4 v = src[i];
                uint32_t h0, l0, h1, l1;
                split2(v.x, v.y, h0, l0);
                split2(v.z, v.w, h1, l1);
                *reinterpret_cast<uint2*>(&g_Bh[o][e * 8 + i * 2]) = make_uint2(h0, h1);
                *reinterpret_cast<uint2*>(&g_Bl[o][e * 8 + i * 2]) = make_uint2(l0, l1);
            }
        }
    }
}

// ---------------------------------------------------------------------------
// mid: midp[split] = x @ A_ext^T.  grid (T/128, KSPLIT), 256 thr.
//   x: LDG->reg for chunk c+1 issued before compute(c) (latency hidden).
//   A: cp.async into double-buffered smem (wait_group 1 keeps 1 in flight).
//   smem: xh|xl (128 x S) + 2 x (ah|al) (80 x S) = 82,944 B; 2 CTAs/SM.
// ---------------------------------------------------------------------------
#define AROWS_SM   80
#define ABUF_BYTES (2 * AROWS_SM * S * 2)           // hi+lo per buffer: 23,040
#define MID_DSM    (2 * 128 * S * 2 + 2 * ABUF_BYTES)   // 82,944

__global__ __launch_bounds__(256, 2)
void mid_kernel(const float* __restrict__ x)
{
    extern __shared__ __align__(16) uint16_t sm_mid[];
    const uint32_t base = smem_u32(sm_mid);
    uint32_t* xh32 = reinterpret_cast<uint32_t*>(sm_mid);
    uint32_t* xl32 = xh32 + 128 * (S / 2);
    const uint32_t xh_b = base;
    const uint32_t xl_b = base + 128 * S * 2;
    const uint32_t a0_b = base + 256 * S * 2;       // buf0 hi; lo at +AROWS_SM*S*2

    const int tid  = threadIdx.x;
    const int w    = tid >> 5;
    const int lane = tid & 31;
    const int g    = lane >> 2;
    const int tig  = lane & 3;
    const int t0   = blockIdx.x * 128;
    const int split = blockIdx.y;
    const int kbase = split * (D_DIM / KSPLIT);

    // ldmatrix per-lane address components
    const int arow = (lane & 7) + ((lane >> 3) & 1) * 8;   // A-frag (x tile)
    const int acol = (lane >> 4) * 8;
    const int brow = (lane & 7) + (lane >> 4) * 8;         // B-frag (A_ext tile)
    const int bcol = ((lane >> 3) & 1) * 8;
    const int brow2 = 64 + (lane & 7);                     // single-tile x2 rows
    const int bcol2 = ((lane >> 3) & 1) * 8;
    const uint32_t axh = xh_b + (uint32_t)(((w * 16 + arow) * S + acol) * 2);
    const uint32_t axl = xl_b + (uint32_t)(((w * 16 + arow) * S + acol) * 2);
    const uint32_t bah  = a0_b + (uint32_t)((brow * S + bcol) * 2);
    const uint32_t bal  = a0_b + (uint32_t)(AROWS_SM * S * 2 + (brow * S + bcol) * 2);
    const uint32_t bah2 = a0_b + (uint32_t)((brow2 * S + bcol2) * 2);
    const uint32_t bal2 = a0_b + (uint32_t)(AROWS_SM * S * 2 + (brow2 * S + bcol2) * 2);

    // staging indices
    const int xr = tid >> 4, xq = tid & 15;       // x: row, float4-col

    // A cp.async op map: 1152 = 2(hl) * 72 rows * 8 uint4-cols
    int cp_hl[5], cp_row[5], cp_c4[5];
    bool cp_on[5];
    #pragma unroll
    for (int p = 0; p < 5; p++) {
        int idx = tid + p * 256;
        cp_on[p] = idx < 1152;
        int hl = idx >= 576 ? 1 : 0;
        int r2 = idx - hl * 576;
        cp_hl[p] = hl;
        cp_row[p] = r2 >> 3;
        cp_c4[p] = r2 & 7;
    }

    const int NCHUNK = (D_DIM / KSPLIT) / 64;     // 16

    // prologue: A(0) cp.async into buf0; x(0) LDG into regs
    {
        const int kq = kbase >> 1;
        #pragma unroll
        for (int p = 0; p < 5; p++) {
            if (cp_on[p]) {
                const uint32_t* src = (cp_hl[p] ? g_Axl[cp_row[p]] : g_Axh[cp_row[p]])
                                      + kq + cp_c4[p] * 4;
                uint32_t dst = a0_b + (uint32_t)(cp_hl[p] * (AROWS_SM * S * 2)
                             + cp_row[p] * (S * 2) + cp_c4[p] * 16);
                CP_ASYNC16(dst, src);
            }
        }
        CP_COMMIT();
    }
    float4 xv[8];
    #pragma unroll
    for (int p = 0; p < 8; p++)
        xv[p] = *reinterpret_cast<const float4*>(
            x + (size_t)(t0 + xr + p * 16) * D_DIM + kbase + xq * 4);

    float acc[9][4] = {};

    for (int c = 0; c < NCHUNK; c++) {
        __syncthreads();   // compute(c-1) done reading x smem & A buf[(c+1)&1]

        // STS x(c) from regs
        #pragma unroll
        for (int p = 0; p < 8; p++) {
            uint32_t h0, l0, h1, l1;
            split2(xv[p].x, xv[p].y, h0, l0);
            split2(xv[p].z, xv[p].w, h1, l1);
            int u = (xr + p * 16) * (S / 2) + xq * 2;
            *reinterpret_cast<uint2*>(&xh32[u]) = make_uint2(h0, h1);
            *reinterpret_cast<uint2*>(&xl32[u]) = make_uint2(l0, l1);
        }

        if (c + 1 < NCHUNK) {
            // issue A(c+1) cp.async into buf[(c+1)&1]
            const int kq = (kbase + (c + 1) * 64) >> 1;
            const uint32_t bufo = (uint32_t)(((c + 1) & 1) * ABUF_BYTES);
            #pragma unroll
            for (int p = 0; p < 5; p++) {
                if (cp_on[p]) {
                    const uint32_t* src = (cp_hl[p] ? g_Axl[cp_row[p]] : g_Axh[cp_row[p]])
                                          + kq + cp_c4[p] * 4;
                    uint32_t dst = a0_b + bufo + (uint32_t)(cp_hl[p] * (AROWS_SM * S * 2)
                                 + cp_row[p] * (S * 2) + cp_c4[p] * 16);
                    CP_ASYNC16(dst, src);
                }
            }
            CP_COMMIT();
            // issue x(c+1) LDG into regs (latency overlaps compute(c))
            const int k1 = kbase + (c + 1) * 64;
            #pragma unroll
            for (int p = 0; p < 8; p++)
                xv[p] = *reinterpret_cast<const float4*>(
                    x + (size_t)(t0 + xr + p * 16) * D_DIM + k1 + xq * 4);
            CP_WAIT1();   // A(c) complete; A(c+1) may stay in flight
        } else {
            CP_WAIT0();   // last chunk: A(c) complete
        }
        __syncthreads();

        const uint32_t aoff = (uint32_t)((c & 1) * ABUF_BYTES);
        #pragma unroll
        for (int ks = 0; ks < 4; ks++) {
            const uint32_t kb = (uint32_t)(ks * 32);   // 16 halves
            uint32_t ah0, ah1, ah2, ah3, al0, al1, al2, al3;
            LDSM_X4(ah0, ah1, ah2, ah3, axh + kb);
            LDSM_X4(al0, al1, al2, al3, axl + kb);
            #pragma unroll
            for (int ntp = 0; ntp < 4; ntp++) {        // tile pairs 0..7
                const uint32_t bo = (uint32_t)(ntp * 16 * S * 2) + kb + aoff;
                uint32_t bh0, bh1, bh2, bh3, bl0, bl1, bl2, bl3;
                LDSM_X4(bh0, bh1, bh2, bh3, bah + bo);
                LDSM_X4(bl0, bl1, bl2, bl3, bal + bo);
                mma_bf16(acc[2 * ntp],     ah0, ah1, ah2, ah3, bh0, bh1);
                mma_bf16(acc[2 * ntp],     ah0, ah1, ah2, ah3, bl0, bl1);
                mma_bf16(acc[2 * ntp],     al0, al1, al2, al3, bh0, bh1);
                mma_bf16(acc[2 * ntp + 1], ah0, ah1, ah2, ah3, bh2, bh3);
                mma_bf16(acc[2 * ntp + 1], ah0, ah1, ah2, ah3, bl2, bl3);
                mma_bf16(acc[2 * ntp + 1], al0, al1, al2, al3, bh2, bh3);
            }
            {   // single tile 8 (cols 64..71, incl. router logits)
                uint32_t bh0, bh1, bl0, bl1;
                LDSM_X2(bh0, bh1, bah2 + kb + aoff);
                LDSM_X2(bl0, bl1, bal2 + kb + aoff);
                mma_bf16(acc[8], ah0, ah1, ah2, ah3, bh0, bh1);
                mma_bf16(acc[8], ah0, ah1, ah2, ah3, bl0, bl1);
                mma_bf16(acc[8], al0, al1, al2, al3, bh0, bh1);
            }
        }
    }

    const int r0 = t0 + w * 16 + g;
    #pragma unroll
    for (int nt = 0; nt < 9; nt++) {
        int col = nt * 8 + 2 * tig;
        *reinterpret_cast<float2*>(&g_midp[split][r0][col]) =
            make_float2(acc[nt][0], acc[nt][1]);
        *reinterpret_cast<float2*>(&g_midp[split][r0 + 8][col]) =
            make_float2(acc[nt][2], acc[nt][3]);
    }
}

// ---------------------------------------------------------------------------
// comb: gates (one lane per token + shfl broadcast) + gmid -> bf16 hi/lo.
// ---------------------------------------------------------------------------
__global__ __launch_bounds__(256)
void comb_kernel(int T)
{
    int idx = blockIdx.x * blockDim.x + threadIdx.x;
    if (idx >= T * 16) return;
    int t = idx >> 4;
    int j = idx & 15;
    int lane = threadIdx.x & 31;

    float g1 = 0.f, g2 = 0.f;
    int i1 = 0, i2 = 0;
    if ((lane & 15) == 0) {
        float l[4];
        #pragma unroll
        for (int e = 0; e < 4; e++) {
            float s = 0.f;
            #pragma unroll
            for (int p = 0; p < KSPLIT; p++) s += g_midp[p][t][64 + e];
            l[e] = s;
        }
        i1 = 0; float v1 = l[0];
        if (l[1] > v1) { v1 = l[1]; i1 = 1; }
        if (l[2] > v1) { v1 = l[2]; i1 = 2; }
        if (l[3] > v1) { v1 = l[3]; i1 = 3; }
        float v2 = -3.4e38f;
        #pragma unroll
        for (int e = 0; e < 4; e++)
            if (e != i1 && l[e] > v2) { v2 = l[e]; i2 = e; }
        float e2  = __expf(v2 - v1);
        float inv = 1.0f / (1.0f + e2);
        g1 = LSCALE * inv;
        g2 = LSCALE * e2 * inv;
    }
    const int src = lane & 16;
    i1 = __shfl_sync(0xffffffffu, i1, src);
    i2 = __shfl_sync(0xffffffffu, i2, src);
    g1 = __shfl_sync(0xffffffffu, g1, src);
    g2 = __shfl_sync(0xffffffffu, g2, src);

    int e_mine = j >> 2;
    float gv = (e_mine == i1) ? g1 : (e_mine == i2) ? g2 : 0.f;

    float4 s = make_float4(0.f, 0.f, 0.f, 0.f);
    #pragma unroll
    for (int p = 0; p < KSPLIT; p++) {
        float4 m = *reinterpret_cast<const float4*>(&g_midp[p][t][j * 4]);
        s.x += m.x; s.y += m.y; s.z += m.z; s.w += m.w;
    }
    uint32_t h0, l0, h1, l1;
    split2(s.x * gv, s.y * gv, h0, l0);
    split2(s.z * gv, s.w * gv, h1, l1);
    *reinterpret_cast<uint2*>(&g_Gh[t][j * 2]) = make_uint2(h0, h1);
    *reinterpret_cast<uint2*>(&g_Gl[t][j * 2]) = make_uint2(l0, l1);
}

// ---------------------------------------------------------------------------
// out: out = gmid @ Bf^T, 128x128 CTA tile, K=64 single shot.
//   Warp grid 4x2: each warp 32 rows x 64 cols (2 m-tiles x 8 n-tiles)
//   -> 12 LDSM.x4 per ks (was 18), 48 total per warp (-33%).
//   smem: gh|gl|bh|bl (each 128 x S) = 72 KB.  grid (O/128, T/128), 256 thr.
// ---------------------------------------------------------------------------
#define OUT_DSM (4 * 128 * S * 2)

__global__ __launch_bounds__(256, 2)
void out_kernel(float* __restrict__ out)
{
    extern __shared__ __align__(16) uint16_t sm_out[];
    const uint32_t base = smem_u32(sm_out);
    uint32_t* gh32 = reinterpret_cast<uint32_t*>(sm_out);
    uint32_t* gl32 = gh32 + 128 * (S / 2);
    uint32_t* bh32 = gl32 + 128 * (S / 2);
    uint32_t* bl32 = bh32 + 128 * (S / 2);
    const uint32_t gh_b = base;
    const uint32_t gl_b = base + 128 * S * 2;
    const uint32_t bh_b = base + 256 * S * 2;
    const uint32_t bl_b = base + 384 * S * 2;

    const int tid  = threadIdx.x;
    const int w    = tid >> 5;
    const int lane = tid & 31;
    const int g    = lane >> 2;
    const int tig  = lane & 3;
    const int wm   = w & 3;          // warp row-group: rows wm*32..+31
    const int wn   = w >> 2;         // warp col-group: cols wn*64..+63
    const int n0   = blockIdx.x * 128;
    const int t0   = blockIdx.y * 128;

    // stage all four tiles via uint4 (16 LDG.128 + 16 STS.128 per thread)
    #pragma unroll
    for (int p = 0; p < 4; p++) {
        int idx = tid + p * 256;        // 0..1023
        int row = idx >> 3;
        int q   = idx & 7;
        int u   = row * (S / 2) + q * 4;
        *reinterpret_cast<uint4*>(&gh32[u]) =
            *reinterpret_cast<const uint4*>(&g_Gh[t0 + row][q * 4]);
        *reinterpret_cast<uint4*>(&gl32[u]) =
            *reinterpret_cast<const uint4*>(&g_Gl[t0 + row][q * 4]);
        *reinterpret_cast<uint4*>(&bh32[u]) =
            *reinterpret_cast<const uint4*>(&g_Bh[n0 + row][q * 4]);
        *reinterpret_cast<uint4*>(&bl32[u]) =
            *reinterpret_cast<const uint4*>(&g_Bl[n0 + row][q * 4]);
    }
    __syncthreads();

    // ldmatrix lane-address components
    const int arow = (lane & 7) + ((lane >> 3) & 1) * 8;   // A frag (G tile)
    const int acol = (lane >> 4) * 8;
    const int brow = (lane & 7) + (lane >> 4) * 8;         // B frag (Bf tile)
    const int bcol = ((lane >> 3) & 1) * 8;
    // A frag bases for the warp's 2 m-tiles
    uint32_t agh[2], agl[2];
    #pragma unroll
    for (int mt = 0; mt < 2; mt++) {
        int r = wm * 32 + mt * 16 + arow;
        agh[mt] = gh_b + (uint32_t)((r * S + acol) * 2);
        agl[mt] = gl_b + (uint32_t)((r * S + acol) * 2);
    }
    // B frag base for the warp's col-group
    const uint32_t bbh = bh_b + (uint32_t)(((wn * 64 + brow) * S + bcol) * 2);
    const uint32_t bbl = bl_b + (uint32_t)(((wn * 64 + brow) * S + bcol) * 2);

    float acc[2][8][4] = {};

    #pragma unroll
    for (int ks = 0; ks < 4; ks++) {
        const uint32_t kb = (uint32_t)(ks * 32);
        uint32_t ah[2][4], al[2][4];
        #pragma unroll
        for (int mt = 0; mt < 2; mt++) {
            LDSM_X4(ah[mt][0], ah[mt][1], ah[mt][2], ah[mt][3], agh[mt] + kb);
            LDSM_X4(al[mt][0], al[mt][1], al[mt][2], al[mt][3], agl[mt] + kb);
        }
        #pragma unroll
        for (int pr = 0; pr < 4; pr++) {               // n-tile pairs
            const uint32_t bo = (uint32_t)(pr * 16 * S * 2) + kb;
            uint32_t bh0, bh1, bh2, bh3, bl0, bl1, bl2, bl3;
            LDSM_X4(bh0, bh1, bh2, bh3, bbh + bo);
            LDSM_X4(bl0, bl1, bl2, bl3, bbl + bo);
            #pragma unroll
            for (int mt = 0; mt < 2; mt++) {
                mma_bf16(acc[mt][2 * pr],     ah[mt][0], ah[mt][1], ah[mt][2], ah[mt][3], bh0, bh1);
                mma_bf16(acc[mt][2 * pr],     ah[mt][0], ah[mt][1], ah[mt][2], ah[mt][3], bl0, bl1);
                mma_bf16(acc[mt][2 * pr],     al[mt][0], al[mt][1], al[mt][2], al[mt][3], bh0, bh1);
                mma_bf16(acc[mt][2 * pr + 1], ah[mt][0], ah[mt][1], ah[mt][2], ah[mt][3], bh2, bh3);
                mma_bf16(acc[mt][2 * pr + 1], ah[mt][0], ah[mt][1], ah[mt][2], ah[mt][3], bl2, bl3);
                mma_bf16(acc[mt][2 * pr + 1], al[mt][0], al[mt][1], al[mt][2], al[mt][3], bh2, bh3);
            }
        }
    }

    #pragma unroll
    for (int mt = 0; mt < 2; mt++) {
        const int r0 = t0 + wm * 32 + mt * 16 + g;
        #pragma unroll
        for (int nt = 0; nt < 8; nt++) {
            int col = n0 + wn * 64 + nt * 8 + 2 * tig;
            *reinterpret_cast<float2*>(out + (size_t)r0 * O_DIM + col) =
                make_float2(acc[mt][nt][0], acc[mt][nt][1]);
            *reinterpret_cast<float2*>(out + (size_t)(r0 + 8) * O_DIM + col) =
                make_float2(acc[mt][nt][2], acc[mt][nt][3]);
        }
    }
}

// ---------------------------------------------------------------------------
// launch
// ---------------------------------------------------------------------------
extern "C" void kernel_launch(void* const* d_in, const int* in_sizes, int n_in,
                              void* d_out, int out_size)
{
    const float* x  = (const float*)d_in[0];   // (T, D)
    const float* rw = (const float*)d_in[1];   // (E, D)
    const float* A  = (const float*)d_in[2];   // (E, R, D) == (64, D)
    const float* B  = (const float*)d_in[3];   // (E, O, R)
    float* out = (float*)d_out;                // (T, O)

    int T = in_sizes[0] / D_DIM;               // 8192

    cudaFuncSetAttribute(mid_kernel, cudaFuncAttributeMaxDynamicSharedMemorySize, MID_DSM);
    cudaFuncSetAttribute(out_kernel, cudaFuncAttributeMaxDynamicSharedMemorySize, OUT_DSM);

    prep_kernel<<<288 + 16, 256>>>(A, rw, B);
    mid_kernel<<<dim3(T / 128, KSPLIT), 256, MID_DSM>>>(x);
    comb_kernel<<<(T * 16 + 255) / 256, 256>>>(T);
    out_kernel<<<dim3(O_DIM / 128, T / 128), 256, OUT_DSM>>>(out);
}